// round 7
// baseline (speedup 1.0000x reference)
#include <cuda_runtime.h>
#include <cstdint>
#include <math.h>

#define TOK   8192
#define EMB_  768
#define FF_   3072
#define HEADS_ 12
#define SEQ_  2048
#define LDQKV 2304

// ---------------- scratch (device globals; no allocation allowed) ----------
__device__ float g_ln  [TOK * EMB_];
__device__ float g_qkv [TOK * LDQKV];
__device__ float g_ctx [TOK * EMB_];
__device__ float g_x2  [TOK * EMB_];
__device__ float g_ffh [(size_t)TOK * FF_];
__device__ float g_wqkv[EMB_ * LDQKV];
__device__ float g_wo  [EMB_ * EMB_];
__device__ float g_w1  [EMB_ * FF_];
__device__ float g_w2  [FF_ * EMB_];

// ---------------- helpers ---------------------------------------------------
__device__ __forceinline__ uint32_t s2u(const void* p) {
    uint32_t a;
    asm("{ .reg .u64 t; cvta.to.shared.u64 t, %1; cvt.u32.u64 %0, t; }" : "=r"(a) : "l"(p));
    return a;
}
__device__ __forceinline__ float tf32r(float x) {
    uint32_t u; asm("cvt.rna.tf32.f32 %0, %1;" : "=r"(u) : "f"(x));
    return __uint_as_float(u);
}
__device__ __forceinline__ float gelu_f(float x) {
    const float c = 0.79788456080286535588f;
    float t = tanhf(c * (x + 0.044715f * x * x * x));
    return 0.5f * x * (1.f + t);
}
__device__ __forceinline__ void mma8(float c[4], const uint32_t a[4],
                                     uint32_t b0, uint32_t b1) {
    asm volatile("mma.sync.aligned.m16n8k8.row.col.f32.tf32.tf32.f32 "
        "{%0,%1,%2,%3}, {%4,%5,%6,%7}, {%8,%9}, {%0,%1,%2,%3};"
        : "+f"(c[0]), "+f"(c[1]), "+f"(c[2]), "+f"(c[3])
        : "r"(a[0]), "r"(a[1]), "r"(a[2]), "r"(a[3]), "r"(b0), "r"(b1));
}

#define CPA16(d, s) \
    asm volatile("cp.async.cg.shared.global [%0], [%1], 16;" :: "r"(d), "l"(s))
#define CPA_COMMIT() asm volatile("cp.async.commit_group;" ::: "memory")
#define CPA_WAIT2()  asm volatile("cp.async.wait_group 2;" ::: "memory")

// ---------------- weight prep -----------------------------------------------
__global__ __launch_bounds__(256) void round_copy(const float* __restrict__ s,
                                                  float* __restrict__ d, int n)
{
    int i = (blockIdx.x * 256 + threadIdx.x) * 4;
    if (i < n) {
        float4 v = *(const float4*)(s + i);
        v.x = tf32r(v.x); v.y = tf32r(v.y); v.z = tf32r(v.z); v.w = tf32r(v.w);
        *(float4*)(d + i) = v;
    }
}
__global__ __launch_bounds__(256) void pack_qkv(const float* __restrict__ wq,
                                                const float* __restrict__ wk,
                                                const float* __restrict__ wv,
                                                float* __restrict__ d)
{
    int i = blockIdx.x * 256 + threadIdx.x;
    int k = i / EMB_, n = i % EMB_;
    d[(size_t)k * LDQKV + n        ] = tf32r(wq[i]);
    d[(size_t)k * LDQKV + n + 768  ] = tf32r(wk[i]);
    d[(size_t)k * LDQKV + n + 1536 ] = tf32r(wv[i]);
}

// ---------------- layernorm --------------------------------------------------
__global__ __launch_bounds__(256) void ln_k(const float* __restrict__ x,
                                            const float* __restrict__ sc,
                                            const float* __restrict__ sh,
                                            float* __restrict__ out)
{
    int row = blockIdx.x;
    const float* xr = x + (size_t)row * EMB_;
    int t = threadIdx.x;
    float v0 = xr[t], v1 = xr[t + 256], v2 = xr[t + 512];

    __shared__ float red[8];
    float s = v0 + v1 + v2;
    #pragma unroll
    for (int o = 16; o; o >>= 1) s += __shfl_xor_sync(0xffffffffu, s, o);
    if ((t & 31) == 0) red[t >> 5] = s;
    __syncthreads();
    float mean = 0.f;
    #pragma unroll
    for (int i = 0; i < 8; i++) mean += red[i];
    mean *= (1.f / 768.f);

    float d0 = v0 - mean, d1 = v1 - mean, d2 = v2 - mean;
    float vs = d0 * d0 + d1 * d1 + d2 * d2;
    #pragma unroll
    for (int o = 16; o; o >>= 1) vs += __shfl_xor_sync(0xffffffffu, vs, o);
    __syncthreads();
    if ((t & 31) == 0) red[t >> 5] = vs;
    __syncthreads();
    float var = 0.f;
    #pragma unroll
    for (int i = 0; i < 8; i++) var += red[i];
    var *= (1.f / 768.f);
    float rstd = rsqrtf(var + 1e-5f);

    float* orow = out + (size_t)row * EMB_;
    orow[t      ] = tf32r(d0 * rstd * sc[t      ] + sh[t      ]);
    orow[t + 256] = tf32r(d1 * rstd * sc[t + 256] + sh[t + 256]);
    orow[t + 512] = tf32r(d2 * rstd * sc[t + 512] + sh[t + 512]);
}

// ---------------- tf32 mma.sync GEMM: C[M,N] = A[M,K] @ B[K,N] -------------
// CTA 128x256 tile, 512 threads = 16 warps (2m x 8n), warp tile 64x32.
// 3-stage cp.async pipeline, K=32/stage. B-traffic per FLOP halved vs 128x128.
#define APITCH 36
#define BPITCH 264
#define A_FLOATS (128 * APITCH)                  // 4608
#define STAGE_FLOATS (A_FLOATS + 32 * BPITCH)    // 4608 + 8448 = 13056
#define NSTG 3
#define GEMM_SMEM (NSTG * STAGE_FLOATS * 4)      // 156672 B

template<int EPI>   // 0 plain; 1 +bias+res; 2 +bias, gelu, tf32-round
__global__ __launch_bounds__(512, 1) void mmagemm(const float* __restrict__ A,
                                                  const float* __restrict__ B,
                                                  const float* __restrict__ bias,
                                                  const float* __restrict__ res,
                                                  float* __restrict__ C,
                                                  int Kd, int N, int ldc, int KT)
{
    extern __shared__ __align__(16) float smf[];
    int tid = threadIdx.x, lane = tid & 31, w = tid >> 5;
    int wm = w >> 3, wn = w & 7;       // 2 x 8 warp grid
    int bm = blockIdx.y, bn = blockIdx.x;
    int gr = lane >> 2, t4 = lane & 3;

    float acc[4][4][4];
    #pragma unroll
    for (int i = 0; i < 4; i++)
        #pragma unroll
        for (int j = 0; j < 4; j++)
            #pragma unroll
            for (int e = 0; e < 4; e++) acc[i][j][e] = 0.f;

    auto issue = [&](int kt) {
        float* st = smf + (kt % NSTG) * STAGE_FLOATS;
        int k0 = kt * 32;
        #pragma unroll
        for (int i = 0; i < 2; i++) {                  // A: 128 x 32 = 1024 chunks
            int chunk = tid + i * 512;
            int row = chunk >> 3, kq = chunk & 7;
            CPA16(s2u(st + row * APITCH + kq * 4),
                  A + (size_t)(bm * 128 + row) * Kd + k0 + kq * 4);
        }
        #pragma unroll
        for (int i = 0; i < 4; i++) {                  // B: 32 x 256 = 2048 chunks
            int chunk = tid + i * 512;
            int kr = chunk >> 6, nq = chunk & 63;
            CPA16(s2u(st + A_FLOATS + kr * BPITCH + nq * 4),
                  B + (size_t)(k0 + kr) * N + bn * 256 + nq * 4);
        }
    };

    issue(0); CPA_COMMIT();
    issue(1); CPA_COMMIT();

    for (int kt = 0; kt < KT; kt++) {
        if (kt + 2 < KT) issue(kt + 2);
        CPA_COMMIT();
        CPA_WAIT2();
        __syncthreads();

        const float* st = smf + (kt % NSTG) * STAGE_FLOATS;
        const uint32_t* As = (const uint32_t*)st;
        const uint32_t* Bs = (const uint32_t*)(st + A_FLOATS);

        #pragma unroll
        for (int kc = 0; kc < 4; kc++) {
            int kb = kc * 8;
            uint32_t a[4][4];
            #pragma unroll
            for (int mt = 0; mt < 4; mt++) {
                int r = wm * 64 + mt * 16 + gr;
                a[mt][0] = As[(r    ) * APITCH + kb + t4    ];
                a[mt][1] = As[(r + 8) * APITCH + kb + t4    ];
                a[mt][2] = As[(r    ) * APITCH + kb + t4 + 4];
                a[mt][3] = As[(r + 8) * APITCH + kb + t4 + 4];
            }
            uint32_t b[4][2];
            #pragma unroll
            for (int nt = 0; nt < 4; nt++) {
                int n = wn * 32 + nt * 8 + gr;
                b[nt][0] = Bs[(kb + t4    ) * BPITCH + n];
                b[nt][1] = Bs[(kb + t4 + 4) * BPITCH + n];
            }
            #pragma unroll
            for (int mt = 0; mt < 4; mt++)
                #pragma unroll
                for (int nt = 0; nt < 4; nt++)
                    mma8(acc[mt][nt], a[mt], b[nt][0], b[nt][1]);
        }
        __syncthreads();
    }

    float bv[4][2];
    if (EPI >= 1) {
        #pragma unroll
        for (int nt = 0; nt < 4; nt++) {
            int col = bn * 256 + wn * 32 + nt * 8 + t4 * 2;
            bv[nt][0] = bias[col]; bv[nt][1] = bias[col + 1];
        }
    }
    #pragma unroll
    for (int mt = 0; mt < 4; mt++) {
        #pragma unroll
        for (int rr = 0; rr < 2; rr++) {
            int row = bm * 128 + wm * 64 + mt * 16 + gr + rr * 8;
            size_t off = (size_t)row * ldc + bn * 256 + wn * 32 + t4 * 2;
            #pragma unroll
            for (int nt = 0; nt < 4; nt++) {
                float v0 = acc[mt][nt][rr * 2 + 0];
                float v1 = acc[mt][nt][rr * 2 + 1];
                if (EPI >= 1) { v0 += bv[nt][0]; v1 += bv[nt][1]; }
                if (EPI == 2) { v0 = tf32r(gelu_f(v0)); v1 = tf32r(gelu_f(v1)); }
                if (EPI == 1) {
                    float2 r2 = *(const float2*)&res[off + nt * 8];
                    v0 += r2.x; v1 += r2.y;
                }
                *(float2*)&C[off + nt * 8] = make_float2(v0, v1);
            }
        }
    }
}

// ---------------- causal flash attention, tf32 mma.sync --------------------
#define AP 68
#define ATTN_SMEM ((64 + 64 + 128) * AP * 4)   // 69632 B

__global__ __launch_bounds__(256) void attn_mma(const float* __restrict__ Q,
                                                const float* __restrict__ K,
                                                const float* __restrict__ V,
                                                float* __restrict__ O)
{
    extern __shared__ __align__(16) float sm[];
    float* Ks = sm;
    float* Vt = sm + 64 * AP;
    float* Ps = sm + 128 * AP;
    const uint32_t* Ku = (const uint32_t*)Ks;
    const uint32_t* Vu = (const uint32_t*)Vt;
    const uint32_t* Pu = (const uint32_t*)Ps;

    int tid = threadIdx.x, lane = tid & 31, w = tid >> 5;
    int gr = lane >> 2, t4 = lane & 3;
    int bh = blockIdx.y, bb = bh / HEADS_, h = bh % HEADS_;
    int q0 = blockIdx.x * 128;
    size_t baseq = (size_t)bb * SEQ_ * LDQKV + (size_t)h * 64;
    size_t baseo = (size_t)bb * SEQ_ * EMB_  + (size_t)h * 64;
    int r = w * 16 + gr;

    for (int i = tid; i < 128 * 64; i += 256) {
        int rr = i >> 6, dd = i & 63;
        Ps[rr * AP + dd] = tf32r(Q[baseq + (size_t)(q0 + rr) * LDQKV + dd] * 0.125f);
    }
    __syncthreads();
    uint32_t qf[8][4];
    #pragma unroll
    for (int kc = 0; kc < 8; kc++) {
        int kb = kc * 8;
        qf[kc][0] = Pu[(r    ) * AP + kb + t4    ];
        qf[kc][1] = Pu[(r + 8) * AP + kb + t4    ];
        qf[kc][2] = Pu[(r    ) * AP + kb + t4 + 4];
        qf[kc][3] = Pu[(r + 8) * AP + kb + t4 + 4];
    }

    float m0 = -1e30f, m1 = -1e30f, l0 = 0.f, l1 = 0.f;
    float o[8][4];
    #pragma unroll
    for (int nt = 0; nt < 8; nt++)
        #pragma unroll
        for (int e = 0; e < 4; e++) o[nt][e] = 0.f;

    int jmaxt = 2 * blockIdx.x + 1;
    int qlo = q0 + r;

    for (int j = 0; j <= jmaxt; j++) {
        __syncthreads();
        for (int i = tid; i < 64 * 64; i += 256) {
            int rr = i >> 6, dd = i & 63;
            size_t g = baseq + (size_t)(j * 64 + rr) * LDQKV + dd;
            Ks[rr * AP + dd] = tf32r(K[g]);
            Vt[dd * AP + rr] = tf32r(V[g]);
        }
        __syncthreads();

        float s[8][4];
        #pragma unroll
        for (int nt = 0; nt < 8; nt++)
            #pragma unroll
            for (int e = 0; e < 4; e++) s[nt][e] = 0.f;
        #pragma unroll
        for (int kc = 0; kc < 8; kc++) {
            int kb = kc * 8;
            #pragma unroll
            for (int nt = 0; nt < 8; nt++) {
                uint32_t b0 = Ku[(nt * 8 + gr) * AP + kb + t4    ];
                uint32_t b1 = Ku[(nt * 8 + gr) * AP + kb + t4 + 4];
                mma8(s[nt], qf[kc], b0, b1);
            }
        }

        if (j * 64 + 63 > q0 + w * 16) {
            #pragma unroll
            for (int nt = 0; nt < 8; nt++) {
                int c0 = j * 64 + nt * 8 + 2 * t4;
                if (c0     > qlo    ) s[nt][0] = -1e30f;
                if (c0 + 1 > qlo    ) s[nt][1] = -1e30f;
                if (c0     > qlo + 8) s[nt][2] = -1e30f;
                if (c0 + 1 > qlo + 8) s[nt][3] = -1e30f;
            }
        }

        float mt0 = -1e30f, mt1 = -1e30f;
        #pragma unroll
        for (int nt = 0; nt < 8; nt++) {
            mt0 = fmaxf(mt0, fmaxf(s[nt][0], s[nt][1]));
            mt1 = fmaxf(mt1, fmaxf(s[nt][2], s[nt][3]));
        }
        mt0 = fmaxf(mt0, __shfl_xor_sync(0xffffffffu, mt0, 1));
        mt0 = fmaxf(mt0, __shfl_xor_sync(0xffffffffu, mt0, 2));
        mt1 = fmaxf(mt1, __shfl_xor_sync(0xffffffffu, mt1, 1));
        mt1 = fmaxf(mt1, __shfl_xor_sync(0xffffffffu, mt1, 2));
        float mn0 = fmaxf(m0, mt0), mn1 = fmaxf(m1, mt1);
        float a0 = __expf(m0 - mn0), a1 = __expf(m1 - mn1);
        float ps0 = 0.f, ps1 = 0.f;
        #pragma unroll
        for (int nt = 0; nt < 8; nt++) {
            s[nt][0] = __expf(s[nt][0] - mn0); ps0 += s[nt][0];
            s[nt][1] = __expf(s[nt][1] - mn0); ps0 += s[nt][1];
            s[nt][2] = __expf(s[nt][2] - mn1); ps1 += s[nt][2];
            s[nt][3] = __expf(s[nt][3] - mn1); ps1 += s[nt][3];
        }
        ps0 += __shfl_xor_sync(0xffffffffu, ps0, 1);
        ps0 += __shfl_xor_sync(0xffffffffu, ps0, 2);
        ps1 += __shfl_xor_sync(0xffffffffu, ps1, 1);
        ps1 += __shfl_xor_sync(0xffffffffu, ps1, 2);
        l0 = l0 * a0 + ps0; l1 = l1 * a1 + ps1;
        m0 = mn0; m1 = mn1;
        #pragma unroll
        for (int nt = 0; nt < 8; nt++) {
            o[nt][0] *= a0; o[nt][1] *= a0; o[nt][2] *= a1; o[nt][3] *= a1;
        }

        #pragma unroll
        for (int nt = 0; nt < 8; nt++) {
            int cc = nt * 8 + 2 * t4;
            *(float2*)&Ps[(r    ) * AP + cc] = make_float2(tf32r(s[nt][0]), tf32r(s[nt][1]));
            *(float2*)&Ps[(r + 8) * AP + cc] = make_float2(tf32r(s[nt][2]), tf32r(s[nt][3]));
        }
        __syncwarp();

        #pragma unroll
        for (int kc = 0; kc < 8; kc++) {
            int kb = kc * 8;
            uint32_t pa[4];
            pa[0] = Pu[(r    ) * AP + kb + t4    ];
            pa[1] = Pu[(r + 8) * AP + kb + t4    ];
            pa[2] = Pu[(r    ) * AP + kb + t4 + 4];
            pa[3] = Pu[(r + 8) * AP + kb + t4 + 4];
            #pragma unroll
            for (int nt = 0; nt < 8; nt++) {
                uint32_t b0 = Vu[(nt * 8 + gr) * AP + kb + t4    ];
                uint32_t b1 = Vu[(nt * 8 + gr) * AP + kb + t4 + 4];
                mma8(o[nt], pa, b0, b1);
            }
        }
    }

    float inv0 = 1.f / l0, inv1 = 1.f / l1;
    size_t off0 = baseo + (size_t)(q0 + r    ) * EMB_;
    size_t off1 = baseo + (size_t)(q0 + r + 8) * EMB_;
    #pragma unroll
    for (int nt = 0; nt < 8; nt++) {
        int cc = nt * 8 + 2 * t4;
        *(float2*)&O[off0 + cc] = make_float2(tf32r(o[nt][0] * inv0), tf32r(o[nt][1] * inv0));
        *(float2*)&O[off1 + cc] = make_float2(tf32r(o[nt][2] * inv1), tf32r(o[nt][3] * inv1));
    }
}

// ---------------- launch ---------------------------------------------------
extern "C" void kernel_launch(void* const* d_in, const int* in_sizes, int n_in,
                              void* d_out, int out_size)
{
    const float* x    = (const float*)d_in[0];
    const float* ln1s = (const float*)d_in[1];
    const float* ln1b = (const float*)d_in[2];
    const float* wq   = (const float*)d_in[3];
    const float* wk   = (const float*)d_in[4];
    const float* wv   = (const float*)d_in[5];
    const float* wo   = (const float*)d_in[6];
    const float* bo   = (const float*)d_in[7];
    const float* ln2s = (const float*)d_in[8];
    const float* ln2b = (const float*)d_in[9];
    const float* w1   = (const float*)d_in[10];
    const float* b1   = (const float*)d_in[11];
    const float* w2   = (const float*)d_in[12];
    const float* b2   = (const float*)d_in[13];
    float* out = (float*)d_out;

    float *ln, *qkv, *ctx, *x2, *ffh, *wqkvr, *wor, *w1r, *w2r;
    cudaGetSymbolAddress((void**)&ln,    g_ln);
    cudaGetSymbolAddress((void**)&qkv,   g_qkv);
    cudaGetSymbolAddress((void**)&ctx,   g_ctx);
    cudaGetSymbolAddress((void**)&x2,    g_x2);
    cudaGetSymbolAddress((void**)&ffh,   g_ffh);
    cudaGetSymbolAddress((void**)&wqkvr, g_wqkv);
    cudaGetSymbolAddress((void**)&wor,   g_wo);
    cudaGetSymbolAddress((void**)&w1r,   g_w1);
    cudaGetSymbolAddress((void**)&w2r,   g_w2);

    cudaFuncSetAttribute(attn_mma, cudaFuncAttributeMaxDynamicSharedMemorySize, ATTN_SMEM);
    cudaFuncSetAttribute(mmagemm<0>, cudaFuncAttributeMaxDynamicSharedMemorySize, GEMM_SMEM);
    cudaFuncSetAttribute(mmagemm<1>, cudaFuncAttributeMaxDynamicSharedMemorySize, GEMM_SMEM);
    cudaFuncSetAttribute(mmagemm<2>, cudaFuncAttributeMaxDynamicSharedMemorySize, GEMM_SMEM);

    pack_qkv<<<2304, 256>>>(wq, wk, wv, wqkvr);
    round_copy<<<576,  256>>>(wo, wor, EMB_ * EMB_);
    round_copy<<<2304, 256>>>(w1, w1r, EMB_ * FF_);
    round_copy<<<2304, 256>>>(w2, w2r, FF_ * EMB_);

    // 1) ln1
    ln_k<<<TOK, 256>>>(x, ln1s, ln1b, ln);
    // 2) fused QKV projection: [8192,768] @ [768,2304]
    mmagemm<0><<<dim3(9, 64), 512, GEMM_SMEM>>>(ln, wqkvr, nullptr, nullptr,
                                                qkv, EMB_, LDQKV, LDQKV, 24);
    // 3) causal attention
    attn_mma<<<dim3(SEQ_ / 128, 4 * HEADS_), 256, ATTN_SMEM>>>(
        qkv + 0, qkv + 768, qkv + 1536, ctx);
    // 4) output projection + bias + residual
    mmagemm<1><<<dim3(3, 64), 512, GEMM_SMEM>>>(ctx, wor, bo, x, x2,
                                                EMB_, EMB_, EMB_, 24);
    // 5) ln2
    ln_k<<<TOK, 256>>>(x2, ln2s, ln2b, ln);
    // 6) FF1 + bias + GELU
    mmagemm<2><<<dim3(12, 64), 512, GEMM_SMEM>>>(ln, w1r, b1, nullptr, ffh,
                                                 EMB_, FF_, FF_, 24);
    // 7) FF2 + bias + residual -> out
    mmagemm<1><<<dim3(3, 64), 512, GEMM_SMEM>>>(ffh, w2r, b2, x2, out,
                                                FF_, EMB_, EMB_, 96);
}

// round 8
// speedup vs baseline: 1.8374x; 1.8374x over previous
#include <cuda_runtime.h>
#include <cuda_fp16.h>
#include <cstdint>
#include <math.h>

#define TOK   8192
#define EMB_  768
#define FF_   3072
#define HEADS_ 12
#define SEQ_  2048
#define LDQKV 2304

// ---------------- scratch (device globals; no allocation allowed) ----------
__device__ __half g_lnh [TOK * EMB_];
__device__ __half g_qkvh[TOK * LDQKV];
__device__ __half g_ctxh[TOK * EMB_];
__device__ __half g_ffhh[(size_t)TOK * FF_];
__device__ float  g_x2  [TOK * EMB_];
__device__ __half g_wqkvh[LDQKV * EMB_];   // [2304][768]  (wq|wk|wv)^T
__device__ __half g_woh  [EMB_ * EMB_];    // [768][768]
__device__ __half g_w1h  [FF_ * EMB_];     // [3072][768]
__device__ __half g_w2h  [EMB_ * FF_];     // [768][3072]

// ---------------- helpers ---------------------------------------------------
__device__ __forceinline__ uint32_t s2u(const void* p) {
    uint32_t a;
    asm("{ .reg .u64 t; cvta.to.shared.u64 t, %1; cvt.u32.u64 %0, t; }" : "=r"(a) : "l"(p));
    return a;
}
__device__ __forceinline__ float gelu_f(float x) {
    const float c = 0.79788456080286535588f;
    float t = tanhf(c * (x + 0.044715f * x * x * x));
    return 0.5f * x * (1.f + t);
}
__device__ __forceinline__ uint32_t h2u(float a, float b) {
    __half2 h = __floats2half2_rn(a, b);
    return *reinterpret_cast<uint32_t*>(&h);
}
__device__ __forceinline__ void mma16(float c[4], const uint32_t a[4],
                                      uint32_t b0, uint32_t b1) {
    asm volatile("mma.sync.aligned.m16n8k16.row.col.f32.f16.f16.f32 "
        "{%0,%1,%2,%3}, {%4,%5,%6,%7}, {%8,%9}, {%0,%1,%2,%3};"
        : "+f"(c[0]), "+f"(c[1]), "+f"(c[2]), "+f"(c[3])
        : "r"(a[0]), "r"(a[1]), "r"(a[2]), "r"(a[3]), "r"(b0), "r"(b1));
}

#define CPA16(d, s) \
    asm volatile("cp.async.cg.shared.global [%0], [%1], 16;" :: "r"(d), "l"(s))
#define CPA_COMMIT()  asm volatile("cp.async.commit_group;" ::: "memory")
#define CPA_WAIT2()   asm volatile("cp.async.wait_group 2;" ::: "memory")
#define CPA_WAITALL() asm volatile("cp.async.wait_group 0;" ::: "memory")

// ---------------- weight prep: transpose fp32 [K][N] -> half [N][K] --------
__global__ void transp_h(const float* __restrict__ S, __half* __restrict__ D,
                         int K, int N)
{
    __shared__ float t[32][33];
    int n0 = blockIdx.x * 32, k0 = blockIdx.y * 32;
    int tx = threadIdx.x, ty = threadIdx.y;
    #pragma unroll
    for (int i = 0; i < 32; i += 8)
        t[ty + i][tx] = S[(size_t)(k0 + ty + i) * N + n0 + tx];
    __syncthreads();
    #pragma unroll
    for (int i = 0; i < 32; i += 8)
        D[(size_t)(n0 + ty + i) * K + k0 + tx] = __float2half_rn(t[tx][ty + i]);
}

// ---------------- layernorm: fp32 in -> half out ---------------------------
__global__ __launch_bounds__(256) void ln_k(const float* __restrict__ x,
                                            const float* __restrict__ sc,
                                            const float* __restrict__ sh,
                                            __half* __restrict__ out)
{
    int row = blockIdx.x;
    const float* xr = x + (size_t)row * EMB_;
    int t = threadIdx.x;
    float v0 = xr[t], v1 = xr[t + 256], v2 = xr[t + 512];

    __shared__ float red[8];
    float s = v0 + v1 + v2;
    #pragma unroll
    for (int o = 16; o; o >>= 1) s += __shfl_xor_sync(0xffffffffu, s, o);
    if ((t & 31) == 0) red[t >> 5] = s;
    __syncthreads();
    float mean = 0.f;
    #pragma unroll
    for (int i = 0; i < 8; i++) mean += red[i];
    mean *= (1.f / 768.f);

    float d0 = v0 - mean, d1 = v1 - mean, d2 = v2 - mean;
    float vs = d0 * d0 + d1 * d1 + d2 * d2;
    #pragma unroll
    for (int o = 16; o; o >>= 1) vs += __shfl_xor_sync(0xffffffffu, vs, o);
    __syncthreads();
    if ((t & 31) == 0) red[t >> 5] = vs;
    __syncthreads();
    float var = 0.f;
    #pragma unroll
    for (int i = 0; i < 8; i++) var += red[i];
    var *= (1.f / 768.f);
    float rstd = rsqrtf(var + 1e-5f);

    __half* orow = out + (size_t)row * EMB_;
    orow[t      ] = __float2half_rn(d0 * rstd * sc[t      ] + sh[t      ]);
    orow[t + 256] = __float2half_rn(d1 * rstd * sc[t + 256] + sh[t + 256]);
    orow[t + 512] = __float2half_rn(d2 * rstd * sc[t + 512] + sh[t + 512]);
}

// ---------------- fp16 mma.sync GEMM: C[M,N] = A[M,K] @ Bt[N,K]^T ----------
// CTA 128x128, 256 threads = 8 warps (2x4), warp tile 64x32.
// 3-stage cp.async, K=32 halves/stage. u32 pitch 20 (conflict-free).
#define PIT 20
#define B_OFF (128 * PIT)        // 2560 u32
#define STAGE_U32 (2 * 128 * PIT)
#define NSTG 3
#define GEMM_SMEM (NSTG * STAGE_U32 * 4)   // 61440 B

template<int EPI>   // 0: half out + Q-scale(qkv); 1: fp32 out +bias+res; 2: half out +bias+gelu
__global__ __launch_bounds__(256, 2) void mmagemm(const __half* __restrict__ A,
                                                  const __half* __restrict__ Bw,
                                                  const float* __restrict__ bias,
                                                  const float* __restrict__ res,
                                                  void* __restrict__ Cv,
                                                  int Kd, int ldc, int KT)
{
    extern __shared__ __align__(16) uint32_t smu[];
    int tid = threadIdx.x, lane = tid & 31, w = tid >> 5;
    int wm = w >> 2, wn = w & 3;
    int bm = blockIdx.y, bn = blockIdx.x;
    int gr = lane >> 2, t4 = lane & 3;

    float acc[4][4][4];
    #pragma unroll
    for (int i = 0; i < 4; i++)
        #pragma unroll
        for (int j = 0; j < 4; j++)
            #pragma unroll
            for (int e = 0; e < 4; e++) acc[i][j][e] = 0.f;

    auto issue = [&](int kt) {
        uint32_t* st = smu + (kt % NSTG) * STAGE_U32;
        int k0 = kt * 32;
        #pragma unroll
        for (int i = 0; i < 2; i++) {            // A: 128 rows x 4 chunks
            int chunk = tid + i * 256;
            int row = chunk >> 2, q = chunk & 3;
            CPA16(s2u(st + row * PIT + q * 4),
                  A + (size_t)(bm * 128 + row) * Kd + k0 + q * 8);
        }
        #pragma unroll
        for (int i = 0; i < 2; i++) {            // B: 128 n-rows x 4 chunks
            int chunk = tid + i * 256;
            int n = chunk >> 2, q = chunk & 3;
            CPA16(s2u(st + B_OFF + n * PIT + q * 4),
                  Bw + (size_t)(bn * 128 + n) * Kd + k0 + q * 8);
        }
    };

    issue(0); CPA_COMMIT();
    issue(1); CPA_COMMIT();

    for (int kt = 0; kt < KT; kt++) {
        if (kt + 2 < KT) issue(kt + 2);
        CPA_COMMIT();
        CPA_WAIT2();
        __syncthreads();

        const uint32_t* As = smu + (kt % NSTG) * STAGE_U32;
        const uint32_t* Bs = As + B_OFF;

        #pragma unroll
        for (int kc = 0; kc < 2; kc++) {
            int kb = kc * 8;
            uint32_t a[4][4];
            #pragma unroll
            for (int mt = 0; mt < 4; mt++) {
                int r = wm * 64 + mt * 16 + gr;
                a[mt][0] = As[(r    ) * PIT + kb + t4    ];
                a[mt][1] = As[(r + 8) * PIT + kb + t4    ];
                a[mt][2] = As[(r    ) * PIT + kb + t4 + 4];
                a[mt][3] = As[(r + 8) * PIT + kb + t4 + 4];
            }
            uint32_t b[4][2];
            #pragma unroll
            for (int nt = 0; nt < 4; nt++) {
                int n = wn * 32 + nt * 8 + gr;
                b[nt][0] = Bs[n * PIT + kb + t4    ];
                b[nt][1] = Bs[n * PIT + kb + t4 + 4];
            }
            #pragma unroll
            for (int mt = 0; mt < 4; mt++)
                #pragma unroll
                for (int nt = 0; nt < 4; nt++)
                    mma16(acc[mt][nt], a[mt], b[nt][0], b[nt][1]);
        }
        __syncthreads();
    }

    // ---- epilogue ----
    float scale = 1.f;
    if (EPI == 0) scale = (bn * 128 < 768) ? 0.125f : 1.f;   // Q pre-scale
    float bv[4][2];
    if (EPI >= 1) {
        #pragma unroll
        for (int nt = 0; nt < 4; nt++) {
            int col = bn * 128 + wn * 32 + nt * 8 + t4 * 2;
            bv[nt][0] = bias[col]; bv[nt][1] = bias[col + 1];
        }
    }
    #pragma unroll
    for (int mt = 0; mt < 4; mt++) {
        #pragma unroll
        for (int rr = 0; rr < 2; rr++) {
            int row = bm * 128 + wm * 64 + mt * 16 + gr + rr * 8;
            size_t off = (size_t)row * ldc + bn * 128 + wn * 32 + t4 * 2;
            #pragma unroll
            for (int nt = 0; nt < 4; nt++) {
                float v0 = acc[mt][nt][rr * 2 + 0];
                float v1 = acc[mt][nt][rr * 2 + 1];
                if (EPI == 0) { v0 *= scale; v1 *= scale; }
                if (EPI >= 1) { v0 += bv[nt][0]; v1 += bv[nt][1]; }
                if (EPI == 2) { v0 = gelu_f(v0); v1 = gelu_f(v1); }
                if (EPI == 1) {
                    float2 r2 = *(const float2*)&res[off + nt * 8];
                    *(float2*)&((float*)Cv)[off + nt * 8] =
                        make_float2(v0 + r2.x, v1 + r2.y);
                } else {
                    *reinterpret_cast<uint32_t*>((__half*)Cv + off + nt * 8) = h2u(v0, v1);
                }
            }
        }
    }
}

// ---------------- causal flash attention, fp16 mma.sync --------------------
// BQ=128 (8 warps x 16 rows), BK=64, D=64.
#define ATP 36   // u32 pitch
#define ATTN_SMEM ((64 + 64 + 128) * ATP * 4)   // 36864 B

__global__ __launch_bounds__(256, 2) void attn_mma(const __half* __restrict__ Q,
                                                   const __half* __restrict__ K,
                                                   const __half* __restrict__ V,
                                                   __half* __restrict__ O)
{
    extern __shared__ __align__(16) uint32_t smu[];
    uint32_t* Ks32 = smu;                 // [key 64][d2 32 +4]
    uint32_t* Vt32 = smu + 64 * ATP;      // [d 64][key2 32 +4]
    uint32_t* P32  = smu + 128 * ATP;     // [row 128][32 +4]  (Q stage, then P)

    int tid = threadIdx.x, lane = tid & 31, w = tid >> 5;
    int gr = lane >> 2, t4 = lane & 3;
    int bh = blockIdx.y, bb = bh / HEADS_, h = bh % HEADS_;
    int q0 = blockIdx.x * 128;
    size_t baseq = (size_t)bb * SEQ_ * LDQKV + (size_t)h * 64;   // halves
    size_t baseo = (size_t)bb * SEQ_ * EMB_  + (size_t)h * 64;
    int r = w * 16 + gr;

    // stage Q (already scaled by 0.125 in qkv epilogue)
    for (int i = tid; i < 1024; i += 256) {
        int row = i >> 3, q = i & 7;
        CPA16(s2u(P32 + row * ATP + q * 4),
              Q + baseq + (size_t)(q0 + row) * LDQKV + q * 8);
    }
    CPA_COMMIT(); CPA_WAITALL();
    __syncthreads();
    uint32_t qf[4][4];
    #pragma unroll
    for (int kc = 0; kc < 4; kc++) {
        int kb = kc * 8;
        qf[kc][0] = P32[(r    ) * ATP + kb + t4    ];
        qf[kc][1] = P32[(r + 8) * ATP + kb + t4    ];
        qf[kc][2] = P32[(r    ) * ATP + kb + t4 + 4];
        qf[kc][3] = P32[(r + 8) * ATP + kb + t4 + 4];
    }

    float m0 = -1e30f, m1 = -1e30f, l0 = 0.f, l1 = 0.f;
    float o[8][4];
    #pragma unroll
    for (int nt = 0; nt < 8; nt++)
        #pragma unroll
        for (int e = 0; e < 4; e++) o[nt][e] = 0.f;

    int jmaxt = 2 * blockIdx.x + 1;
    int qlo = q0 + r;
    int kp  = (lane >> 2) | ((w & 3) << 3);       // V-transpose lane remap
    int d2b = (lane & 3)  | ((w >> 2) << 2);

    for (int j = 0; j <= jmaxt; j++) {
        __syncthreads();   // prior readers of Ks/Vt/P32 done
        // K tile via cp.async
        for (int i = tid; i < 512; i += 256) {
            int row = i >> 3, q = i & 7;
            CPA16(s2u(Ks32 + row * ATP + q * 4),
                  K + baseq + (size_t)(j * 64 + row) * LDQKV + q * 8);
        }
        CPA_COMMIT();
        // V tile: transpose-pack into Vt32[d][key2]  (conflict-free STS)
        {
            const uint32_t* vg0 = (const uint32_t*)(V + baseq + (size_t)(j * 64 + 2 * kp) * LDQKV);
            const uint32_t* vg1 = vg0 + LDQKV / 2;
            #pragma unroll
            for (int it = 0; it < 4; it++) {
                int d2 = d2b + it * 8;
                uint32_t v0 = vg0[d2];
                uint32_t v1 = vg1[d2];
                Vt32[(2 * d2    ) * ATP + kp] = __byte_perm(v0, v1, 0x5410);
                Vt32[(2 * d2 + 1) * ATP + kp] = __byte_perm(v0, v1, 0x7632);
            }
        }
        CPA_WAITALL();
        __syncthreads();

        // S = Q K^T
        float s[8][4];
        #pragma unroll
        for (int nt = 0; nt < 8; nt++)
            #pragma unroll
            for (int e = 0; e < 4; e++) s[nt][e] = 0.f;
        #pragma unroll
        for (int kc = 0; kc < 4; kc++) {
            int kb = kc * 8;
            #pragma unroll
            for (int nt = 0; nt < 8; nt++) {
                uint32_t b0 = Ks32[(nt * 8 + gr) * ATP + kb + t4    ];
                uint32_t b1 = Ks32[(nt * 8 + gr) * ATP + kb + t4 + 4];
                mma16(s[nt], qf[kc], b0, b1);
            }
        }

        // causal mask
        if (j * 64 + 63 > q0 + w * 16) {
            #pragma unroll
            for (int nt = 0; nt < 8; nt++) {
                int c0 = j * 64 + nt * 8 + 2 * t4;
                if (c0     > qlo    ) s[nt][0] = -1e30f;
                if (c0 + 1 > qlo    ) s[nt][1] = -1e30f;
                if (c0     > qlo + 8) s[nt][2] = -1e30f;
                if (c0 + 1 > qlo + 8) s[nt][3] = -1e30f;
            }
        }

        // online softmax (rows r and r+8; reduce over t4 quad)
        float mt0 = -1e30f, mt1 = -1e30f;
        #pragma unroll
        for (int nt = 0; nt < 8; nt++) {
            mt0 = fmaxf(mt0, fmaxf(s[nt][0], s[nt][1]));
            mt1 = fmaxf(mt1, fmaxf(s[nt][2], s[nt][3]));
        }
        mt0 = fmaxf(mt0, __shfl_xor_sync(0xffffffffu, mt0, 1));
        mt0 = fmaxf(mt0, __shfl_xor_sync(0xffffffffu, mt0, 2));
        mt1 = fmaxf(mt1, __shfl_xor_sync(0xffffffffu, mt1, 1));
        mt1 = fmaxf(mt1, __shfl_xor_sync(0xffffffffu, mt1, 2));
        float mn0 = fmaxf(m0, mt0), mn1 = fmaxf(m1, mt1);
        float a0 = __expf(m0 - mn0), a1 = __expf(m1 - mn1);
        float ps0 = 0.f, ps1 = 0.f;
        #pragma unroll
        for (int nt = 0; nt < 8; nt++) {
            s[nt][0] = __expf(s[nt][0] - mn0); ps0 += s[nt][0];
            s[nt][1] = __expf(s[nt][1] - mn0); ps0 += s[nt][1];
            s[nt][2] = __expf(s[nt][2] - mn1); ps1 += s[nt][2];
            s[nt][3] = __expf(s[nt][3] - mn1); ps1 += s[nt][3];
        }
        ps0 += __shfl_xor_sync(0xffffffffu, ps0, 1);
        ps0 += __shfl_xor_sync(0xffffffffu, ps0, 2);
        ps1 += __shfl_xor_sync(0xffffffffu, ps1, 1);
        ps1 += __shfl_xor_sync(0xffffffffu, ps1, 2);
        l0 = l0 * a0 + ps0; l1 = l1 * a1 + ps1;
        m0 = mn0; m1 = mn1;
        #pragma unroll
        for (int nt = 0; nt < 8; nt++) {
            o[nt][0] *= a0; o[nt][1] *= a0; o[nt][2] *= a1; o[nt][3] *= a1;
        }

        // P -> half pairs in warp-private rows
        #pragma unroll
        for (int nt = 0; nt < 8; nt++) {
            P32[(r    ) * ATP + nt * 4 + t4] = h2u(s[nt][0], s[nt][1]);
            P32[(r + 8) * ATP + nt * 4 + t4] = h2u(s[nt][2], s[nt][3]);
        }
        __syncwarp();

        // O += P V
        #pragma unroll
        for (int kc = 0; kc < 4; kc++) {
            int kb = kc * 8;
            uint32_t pa[4];
            pa[0] = P32[(r    ) * ATP + kb + t4    ];
            pa[1] = P32[(r + 8) * ATP + kb + t4    ];
            pa[2] = P32[(r    ) * ATP + kb + t4 + 4];
            pa[3] = P32[(r + 8) * ATP + kb + t4 + 4];
            #pragma unroll
            for (int nt = 0; nt < 8; nt++) {
                uint32_t b0 = Vt32[(nt * 8 + gr) * ATP + kb + t4    ];
                uint32_t b1 = Vt32[(nt * 8 + gr) * ATP + kb + t4 + 4];
                mma16(o[nt], pa, b0, b1);
            }
        }
    }

    float inv0 = 1.f / l0, inv1 = 1.f / l1;
    uint32_t* O0 = (uint32_t*)(O + baseo + (size_t)(q0 + r    ) * EMB_);
    uint32_t* O1 = (uint32_t*)(O + baseo + (size_t)(q0 + r + 8) * EMB_);
    #pragma unroll
    for (int nt = 0; nt < 8; nt++) {
        O0[nt * 4 + t4] = h2u(o[nt][0] * inv0, o[nt][1] * inv0);
        O1[nt * 4 + t4] = h2u(o[nt][2] * inv1, o[nt][3] * inv1);
    }
}

// ---------------- launch ---------------------------------------------------
extern "C" void kernel_launch(void* const* d_in, const int* in_sizes, int n_in,
                              void* d_out, int out_size)
{
    const float* x    = (const float*)d_in[0];
    const float* ln1s = (const float*)d_in[1];
    const float* ln1b = (const float*)d_in[2];
    const float* wq   = (const float*)d_in[3];
    const float* wk   = (const float*)d_in[4];
    const float* wv   = (const float*)d_in[5];
    const float* wo   = (const float*)d_in[6];
    const float* bo   = (const float*)d_in[7];
    const float* ln2s = (const float*)d_in[8];
    const float* ln2b = (const float*)d_in[9];
    const float* w1   = (const float*)d_in[10];
    const float* b1   = (const float*)d_in[11];
    const float* w2   = (const float*)d_in[12];
    const float* b2   = (const float*)d_in[13];
    float* out = (float*)d_out;

    __half *lnh, *qkvh, *ctxh, *ffhh, *wqkvh, *woh, *w1h, *w2h;
    float *x2;
    cudaGetSymbolAddress((void**)&lnh,   g_lnh);
    cudaGetSymbolAddress((void**)&qkvh,  g_qkvh);
    cudaGetSymbolAddress((void**)&ctxh,  g_ctxh);
    cudaGetSymbolAddress((void**)&ffhh,  g_ffhh);
    cudaGetSymbolAddress((void**)&x2,    g_x2);
    cudaGetSymbolAddress((void**)&wqkvh, g_wqkvh);
    cudaGetSymbolAddress((void**)&woh,   g_woh);
    cudaGetSymbolAddress((void**)&w1h,   g_w1h);
    cudaGetSymbolAddress((void**)&w2h,   g_w2h);

    cudaFuncSetAttribute(attn_mma, cudaFuncAttributeMaxDynamicSharedMemorySize, ATTN_SMEM);
    cudaFuncSetAttribute(mmagemm<0>, cudaFuncAttributeMaxDynamicSharedMemorySize, GEMM_SMEM);
    cudaFuncSetAttribute(mmagemm<1>, cudaFuncAttributeMaxDynamicSharedMemorySize, GEMM_SMEM);
    cudaFuncSetAttribute(mmagemm<2>, cudaFuncAttributeMaxDynamicSharedMemorySize, GEMM_SMEM);

    dim3 tb(32, 8);
    // weight prep: fp32 [K][N] -> half [N][K]
    transp_h<<<dim3(24, 24), tb>>>(wq, wqkvh + 0 * EMB_ * EMB_, EMB_, EMB_);
    transp_h<<<dim3(24, 24), tb>>>(wk, wqkvh + 1 * EMB_ * EMB_, EMB_, EMB_);
    transp_h<<<dim3(24, 24), tb>>>(wv, wqkvh + 2 * EMB_ * EMB_, EMB_, EMB_);
    transp_h<<<dim3(24, 24), tb>>>(wo, woh, EMB_, EMB_);
    transp_h<<<dim3(96, 24), tb>>>(w1, w1h, EMB_, FF_);
    transp_h<<<dim3(24, 96), tb>>>(w2, w2h, FF_, EMB_);

    // 1) ln1 -> half
    ln_k<<<TOK, 256>>>(x, ln1s, ln1b, lnh);
    // 2) fused QKV projection (Q pre-scaled by 0.125) -> half qkv
    mmagemm<0><<<dim3(18, 64), 256, GEMM_SMEM>>>(lnh, wqkvh, nullptr, nullptr,
                                                 qkvh, EMB_, LDQKV, 24);
    // 3) causal attention (fp16 tensor cores) -> half ctx
    attn_mma<<<dim3(SEQ_ / 128, 4 * HEADS_), 256, ATTN_SMEM>>>(
        qkvh + 0, qkvh + 768, qkvh + 1536, ctxh);
    // 4) output projection + bias + residual -> fp32 x2
    mmagemm<1><<<dim3(6, 64), 256, GEMM_SMEM>>>(ctxh, woh, bo, x, x2,
                                                EMB_, EMB_, 24);
    // 5) ln2 -> half
    ln_k<<<TOK, 256>>>(x2, ln2s, ln2b, lnh);
    // 6) FF1 + bias + GELU -> half ffh
    mmagemm<2><<<dim3(24, 64), 256, GEMM_SMEM>>>(lnh, w1h, b1, nullptr, ffhh,
                                                 EMB_, FF_, 24);
    // 7) FF2 + bias + residual -> fp32 out
    mmagemm<1><<<dim3(6, 64), 256, GEMM_SMEM>>>(ffhh, w2h, b2, x2, out,
                                                FF_, EMB_, 96);
}

// round 9
// speedup vs baseline: 1.8805x; 1.0235x over previous
#include <cuda_runtime.h>
#include <cuda_fp16.h>
#include <cstdint>
#include <math.h>

#define TOK   8192
#define EMB_  768
#define FF_   3072
#define HEADS_ 12
#define SEQ_  2048
#define LDQKV 2304

// ---------------- scratch (device globals; no allocation allowed) ----------
__device__ __half g_lnh [TOK * EMB_];
__device__ __half g_qkvh[TOK * LDQKV];
__device__ __half g_ctxh[TOK * EMB_];
__device__ __half g_ffhh[(size_t)TOK * FF_];
__device__ float  g_x2  [TOK * EMB_];
__device__ __half g_wqkvh[LDQKV * EMB_];   // [2304][768]  (wq|wk|wv)^T
__device__ __half g_woh  [EMB_ * EMB_];
__device__ __half g_w1h  [FF_ * EMB_];
__device__ __half g_w2h  [EMB_ * FF_];

// ---------------- helpers ---------------------------------------------------
__device__ __forceinline__ uint32_t s2u(const void* p) {
    uint32_t a;
    asm("{ .reg .u64 t; cvta.to.shared.u64 t, %1; cvt.u32.u64 %0, t; }" : "=r"(a) : "l"(p));
    return a;
}
__device__ __forceinline__ float gelu_f(float x) {
    const float c = 0.79788456080286535588f;
    float t = tanhf(c * (x + 0.044715f * x * x * x));
    return 0.5f * x * (1.f + t);
}
__device__ __forceinline__ uint32_t h2u(float a, float b) {
    __half2 h = __floats2half2_rn(a, b);
    return *reinterpret_cast<uint32_t*>(&h);
}
__device__ __forceinline__ void mma16(float c[4], const uint32_t a[4],
                                      uint32_t b0, uint32_t b1) {
    asm volatile("mma.sync.aligned.m16n8k16.row.col.f32.f16.f16.f32 "
        "{%0,%1,%2,%3}, {%4,%5,%6,%7}, {%8,%9}, {%0,%1,%2,%3};"
        : "+f"(c[0]), "+f"(c[1]), "+f"(c[2]), "+f"(c[3])
        : "r"(a[0]), "r"(a[1]), "r"(a[2]), "r"(a[3]), "r"(b0), "r"(b1));
}
#define LDSM4(d0, d1, d2, d3, addr) \
    asm volatile("ldmatrix.sync.aligned.m8n8.x4.shared.b16 {%0,%1,%2,%3}, [%4];" \
        : "=r"(d0), "=r"(d1), "=r"(d2), "=r"(d3) : "r"(addr))

#define CPA16(d, s) \
    asm volatile("cp.async.cg.shared.global [%0], [%1], 16;" :: "r"(d), "l"(s))
#define CPA_COMMIT()  asm volatile("cp.async.commit_group;" ::: "memory")
#define CPA_WAIT2()   asm volatile("cp.async.wait_group 2;" ::: "memory")
#define CPA_WAITALL() asm volatile("cp.async.wait_group 0;" ::: "memory")

// ---------------- fused weight prep: 6 transposes in one kernel ------------
__global__ void prep_all(const float* __restrict__ wq, const float* __restrict__ wk,
                         const float* __restrict__ wv, const float* __restrict__ wo,
                         const float* __restrict__ w1, const float* __restrict__ w2,
                         __half* __restrict__ wqkvh, __half* __restrict__ woh,
                         __half* __restrict__ w1h,  __half* __restrict__ w2h)
{
    __shared__ float t[32][33];
    int bid = blockIdx.x;
    const float* S; __half* D; int K, N, n0, k0;
    if (bid < 2304) {                      // wq/wk/wv/wo: 768x768, 24x24 tiles
        int m = bid / 576, tt = bid % 576;
        S = (m == 0) ? wq : (m == 1) ? wk : (m == 2) ? wv : wo;
        D = (m == 3) ? woh : wqkvh + (size_t)m * EMB_ * EMB_;
        K = EMB_; N = EMB_;
        n0 = (tt % 24) * 32; k0 = (tt / 24) * 32;
    } else if (bid < 4608) {               // w1: K=768, N=3072
        int tt = bid - 2304;
        S = w1; D = w1h; K = EMB_; N = FF_;
        n0 = (tt % 96) * 32; k0 = (tt / 96) * 32;
    } else {                               // w2: K=3072, N=768
        int tt = bid - 4608;
        S = w2; D = w2h; K = FF_; N = EMB_;
        n0 = (tt % 24) * 32; k0 = (tt / 24) * 32;
    }
    int tx = threadIdx.x, ty = threadIdx.y;
    #pragma unroll
    for (int i = 0; i < 32; i += 8)
        t[ty + i][tx] = S[(size_t)(k0 + ty + i) * N + n0 + tx];
    __syncthreads();
    #pragma unroll
    for (int i = 0; i < 32; i += 8)
        D[(size_t)(n0 + ty + i) * K + k0 + tx] = __float2half_rn(t[tx][ty + i]);
}

// ---------------- layernorm: fp32 in -> half out ---------------------------
__global__ __launch_bounds__(256) void ln_k(const float* __restrict__ x,
                                            const float* __restrict__ sc,
                                            const float* __restrict__ sh,
                                            __half* __restrict__ out)
{
    int row = blockIdx.x;
    const float* xr = x + (size_t)row * EMB_;
    int t = threadIdx.x;
    float v0 = xr[t], v1 = xr[t + 256], v2 = xr[t + 512];

    __shared__ float red[8];
    float s = v0 + v1 + v2;
    #pragma unroll
    for (int o = 16; o; o >>= 1) s += __shfl_xor_sync(0xffffffffu, s, o);
    if ((t & 31) == 0) red[t >> 5] = s;
    __syncthreads();
    float mean = 0.f;
    #pragma unroll
    for (int i = 0; i < 8; i++) mean += red[i];
    mean *= (1.f / 768.f);

    float d0 = v0 - mean, d1 = v1 - mean, d2 = v2 - mean;
    float vs = d0 * d0 + d1 * d1 + d2 * d2;
    #pragma unroll
    for (int o = 16; o; o >>= 1) vs += __shfl_xor_sync(0xffffffffu, vs, o);
    __syncthreads();
    if ((t & 31) == 0) red[t >> 5] = vs;
    __syncthreads();
    float var = 0.f;
    #pragma unroll
    for (int i = 0; i < 8; i++) var += red[i];
    var *= (1.f / 768.f);
    float rstd = rsqrtf(var + 1e-5f);

    __half* orow = out + (size_t)row * EMB_;
    orow[t      ] = __float2half_rn(d0 * rstd * sc[t      ] + sh[t      ]);
    orow[t + 256] = __float2half_rn(d1 * rstd * sc[t + 256] + sh[t + 256]);
    orow[t + 512] = __float2half_rn(d2 * rstd * sc[t + 512] + sh[t + 512]);
}

// ---------------- fp16 mma.sync GEMM: C[M,N] = A[M,K] @ Bt[N,K]^T ----------
// CTA 128x128, 256 threads = 8 warps (2x4), warp tile 64x32.
// 3-stage cp.async, K=32 halves/stage, ldmatrix fragment loads.
#define PIT 20
#define B_OFF (128 * PIT)
#define STAGE_U32 (2 * 128 * PIT)
#define NSTG 3
#define GEMM_SMEM (NSTG * STAGE_U32 * 4)   // 61440 B

template<int EPI>   // 0: half out + Q-scale(qkv); 1: fp32 out +bias+res; 2: half out +bias+gelu
__global__ __launch_bounds__(256, 2) void mmagemm(const __half* __restrict__ A,
                                                  const __half* __restrict__ Bw,
                                                  const float* __restrict__ bias,
                                                  const float* __restrict__ res,
                                                  void* __restrict__ Cv,
                                                  int Kd, int ldc, int KT)
{
    extern __shared__ __align__(16) uint32_t smu[];
    int tid = threadIdx.x, lane = tid & 31, w = tid >> 5;
    int wm = w >> 2, wn = w & 3;
    int bm = blockIdx.y, bn = blockIdx.x;
    int gr = lane >> 2, t4 = lane & 3;
    int lrow = lane & 15;                      // ldmatrix row within 16
    int lcol = (lane & 16) ? 4 : 0;            // ldmatrix u32 col offset

    float acc[4][4][4];
    #pragma unroll
    for (int i = 0; i < 4; i++)
        #pragma unroll
        for (int j = 0; j < 4; j++)
            #pragma unroll
            for (int e = 0; e < 4; e++) acc[i][j][e] = 0.f;

    auto issue = [&](int kt) {
        uint32_t* st = smu + (kt % NSTG) * STAGE_U32;
        int k0 = kt * 32;
        #pragma unroll
        for (int i = 0; i < 2; i++) {
            int chunk = tid + i * 256;
            int row = chunk >> 2, q = chunk & 3;
            CPA16(s2u(st + row * PIT + q * 4),
                  A + (size_t)(bm * 128 + row) * Kd + k0 + q * 8);
        }
        #pragma unroll
        for (int i = 0; i < 2; i++) {
            int chunk = tid + i * 256;
            int n = chunk >> 2, q = chunk & 3;
            CPA16(s2u(st + B_OFF + n * PIT + q * 4),
                  Bw + (size_t)(bn * 128 + n) * Kd + k0 + q * 8);
        }
    };

    issue(0); CPA_COMMIT();
    issue(1); CPA_COMMIT();

    for (int kt = 0; kt < KT; kt++) {
        if (kt + 2 < KT) issue(kt + 2);
        CPA_COMMIT();
        CPA_WAIT2();
        __syncthreads();

        const uint32_t* As = smu + (kt % NSTG) * STAGE_U32;
        uint32_t a_base = s2u(As + (wm * 64 + lrow) * PIT + lcol);
        uint32_t b_base = s2u(As + B_OFF + (wn * 32 + lrow) * PIT + lcol);

        #pragma unroll
        for (int kc = 0; kc < 2; kc++) {
            uint32_t kB = kc * 32;             // byte offset of kb
            uint32_t a[4][4];
            #pragma unroll
            for (int mt = 0; mt < 4; mt++)
                LDSM4(a[mt][0], a[mt][1], a[mt][2], a[mt][3],
                      a_base + mt * (16 * PIT * 4) + kB);
            uint32_t b[4][2];
            #pragma unroll
            for (int ntp = 0; ntp < 2; ntp++)
                LDSM4(b[2 * ntp][0], b[2 * ntp + 1][0],
                      b[2 * ntp][1], b[2 * ntp + 1][1],
                      b_base + ntp * (16 * PIT * 4) + kB);
            #pragma unroll
            for (int mt = 0; mt < 4; mt++)
                #pragma unroll
                for (int nt = 0; nt < 4; nt++)
                    mma16(acc[mt][nt], a[mt], b[nt][0], b[nt][1]);
        }
        __syncthreads();
    }

    // ---- epilogue ----
    float scale = 1.f;
    if (EPI == 0) scale = (bn * 128 < 768) ? 0.125f : 1.f;
    float bv[4][2];
    if (EPI >= 1) {
        #pragma unroll
        for (int nt = 0; nt < 4; nt++) {
            int col = bn * 128 + wn * 32 + nt * 8 + t4 * 2;
            bv[nt][0] = bias[col]; bv[nt][1] = bias[col + 1];
        }
    }
    #pragma unroll
    for (int mt = 0; mt < 4; mt++) {
        #pragma unroll
        for (int rr = 0; rr < 2; rr++) {
            int row = bm * 128 + wm * 64 + mt * 16 + gr + rr * 8;
            size_t off = (size_t)row * ldc + bn * 128 + wn * 32 + t4 * 2;
            #pragma unroll
            for (int nt = 0; nt < 4; nt++) {
                float v0 = acc[mt][nt][rr * 2 + 0];
                float v1 = acc[mt][nt][rr * 2 + 1];
                if (EPI == 0) { v0 *= scale; v1 *= scale; }
                if (EPI >= 1) { v0 += bv[nt][0]; v1 += bv[nt][1]; }
                if (EPI == 2) { v0 = gelu_f(v0); v1 = gelu_f(v1); }
                if (EPI == 1) {
                    float2 r2 = *(const float2*)&res[off + nt * 8];
                    *(float2*)&((float*)Cv)[off + nt * 8] =
                        make_float2(v0 + r2.x, v1 + r2.y);
                } else {
                    *reinterpret_cast<uint32_t*>((__half*)Cv + off + nt * 8) = h2u(v0, v1);
                }
            }
        }
    }
}

// ---------------- causal flash attention, fp16 mma.sync --------------------
// BQ=128, BK=64, D=64. Q frags + P fully in registers; K,V^T in smem (LDSM).
#define ATP 36   // u32 pitch
#define ATTN_SMEM (128 * ATP * 4)   // 18432 B

__global__ __launch_bounds__(256, 2) void attn_mma(const __half* __restrict__ Q,
                                                   const __half* __restrict__ K,
                                                   const __half* __restrict__ V,
                                                   __half* __restrict__ O)
{
    extern __shared__ __align__(16) uint32_t smu[];
    uint32_t* Ks32 = smu;                 // [key 64][d2 32 +4]
    uint32_t* Vt32 = smu + 64 * ATP;      // [d 64][key2 32 +4]

    int tid = threadIdx.x, lane = tid & 31, w = tid >> 5;
    int gr = lane >> 2, t4 = lane & 3;
    int lrow = lane & 15;
    int lcol = (lane & 16) ? 4 : 0;
    int bh = blockIdx.y, bb = bh / HEADS_, h = bh % HEADS_;
    int q0 = blockIdx.x * 128;
    size_t baseq = (size_t)bb * SEQ_ * LDQKV + (size_t)h * 64;   // halves
    size_t baseo = (size_t)bb * SEQ_ * EMB_  + (size_t)h * 64;
    int r = w * 16 + gr;

    // stage Q (pre-scaled) into the whole smem buffer, extract frags to regs
    for (int i = tid; i < 1024; i += 256) {
        int row = i >> 3, q = i & 7;
        CPA16(s2u(smu + row * ATP + q * 4),
              Q + baseq + (size_t)(q0 + row) * LDQKV + q * 8);
    }
    CPA_COMMIT(); CPA_WAITALL();
    __syncthreads();
    uint32_t qf[4][4];
    {
        uint32_t qb = s2u(smu + (w * 16 + lrow) * ATP + lcol);
        #pragma unroll
        for (int kc = 0; kc < 4; kc++)
            LDSM4(qf[kc][0], qf[kc][1], qf[kc][2], qf[kc][3], qb + kc * 32);
    }

    float m0 = -1e30f, m1 = -1e30f, l0 = 0.f, l1 = 0.f;
    float o[8][4];
    #pragma unroll
    for (int nt = 0; nt < 8; nt++)
        #pragma unroll
        for (int e = 0; e < 4; e++) o[nt][e] = 0.f;

    int jmaxt = 2 * blockIdx.x + 1;
    int qlo = q0 + r;
    int kp  = (lane >> 2) | ((w & 3) << 3);       // V-transpose lane remap
    int d2b = (lane & 3)  | ((w >> 2) << 2);
    uint32_t kfb = s2u(Ks32 + lrow * ATP + lcol);
    uint32_t vfb = s2u(Vt32 + lrow * ATP + lcol);

    for (int j = 0; j <= jmaxt; j++) {
        __syncthreads();   // prior tile's K/V frag reads done
        for (int i = tid; i < 512; i += 256) {
            int row = i >> 3, q = i & 7;
            CPA16(s2u(Ks32 + row * ATP + q * 4),
                  K + baseq + (size_t)(j * 64 + row) * LDQKV + q * 8);
        }
        CPA_COMMIT();
        {
            const uint32_t* vg0 = (const uint32_t*)(V + baseq + (size_t)(j * 64 + 2 * kp) * LDQKV);
            const uint32_t* vg1 = vg0 + LDQKV / 2;
            #pragma unroll
            for (int it = 0; it < 4; it++) {
                int d2 = d2b + it * 8;
                uint32_t v0 = vg0[d2];
                uint32_t v1 = vg1[d2];
                Vt32[(2 * d2    ) * ATP + kp] = __byte_perm(v0, v1, 0x5410);
                Vt32[(2 * d2 + 1) * ATP + kp] = __byte_perm(v0, v1, 0x7632);
            }
        }
        CPA_WAITALL();
        __syncthreads();

        // S = Q K^T
        float s[8][4];
        #pragma unroll
        for (int nt = 0; nt < 8; nt++)
            #pragma unroll
            for (int e = 0; e < 4; e++) s[nt][e] = 0.f;
        #pragma unroll
        for (int kc = 0; kc < 4; kc++) {
            uint32_t kB = kc * 32;
            uint32_t b[8][2];
            #pragma unroll
            for (int ntp = 0; ntp < 4; ntp++)
                LDSM4(b[2 * ntp][0], b[2 * ntp + 1][0],
                      b[2 * ntp][1], b[2 * ntp + 1][1],
                      kfb + ntp * (16 * ATP * 4) + kB);
            #pragma unroll
            for (int nt = 0; nt < 8; nt++)
                mma16(s[nt], qf[kc], b[nt][0], b[nt][1]);
        }

        // causal mask
        if (j * 64 + 63 > q0 + w * 16) {
            #pragma unroll
            for (int nt = 0; nt < 8; nt++) {
                int c0 = j * 64 + nt * 8 + 2 * t4;
                if (c0     > qlo    ) s[nt][0] = -1e30f;
                if (c0 + 1 > qlo    ) s[nt][1] = -1e30f;
                if (c0     > qlo + 8) s[nt][2] = -1e30f;
                if (c0 + 1 > qlo + 8) s[nt][3] = -1e30f;
            }
        }

        // online softmax (rows r and r+8; reduce over t4 quad)
        float mt0 = -1e30f, mt1 = -1e30f;
        #pragma unroll
        for (int nt = 0; nt < 8; nt++) {
            mt0 = fmaxf(mt0, fmaxf(s[nt][0], s[nt][1]));
            mt1 = fmaxf(mt1, fmaxf(s[nt][2], s[nt][3]));
        }
        mt0 = fmaxf(mt0, __shfl_xor_sync(0xffffffffu, mt0, 1));
        mt0 = fmaxf(mt0, __shfl_xor_sync(0xffffffffu, mt0, 2));
        mt1 = fmaxf(mt1, __shfl_xor_sync(0xffffffffu, mt1, 1));
        mt1 = fmaxf(mt1, __shfl_xor_sync(0xffffffffu, mt1, 2));
        float mn0 = fmaxf(m0, mt0), mn1 = fmaxf(m1, mt1);
        float a0 = __expf(m0 - mn0), a1 = __expf(m1 - mn1);
        float ps0 = 0.f, ps1 = 0.f;
        #pragma unroll
        for (int nt = 0; nt < 8; nt++) {
            s[nt][0] = __expf(s[nt][0] - mn0); ps0 += s[nt][0];
            s[nt][1] = __expf(s[nt][1] - mn0); ps0 += s[nt][1];
            s[nt][2] = __expf(s[nt][2] - mn1); ps1 += s[nt][2];
            s[nt][3] = __expf(s[nt][3] - mn1); ps1 += s[nt][3];
        }
        ps0 += __shfl_xor_sync(0xffffffffu, ps0, 1);
        ps0 += __shfl_xor_sync(0xffffffffu, ps0, 2);
        ps1 += __shfl_xor_sync(0xffffffffu, ps1, 1);
        ps1 += __shfl_xor_sync(0xffffffffu, ps1, 2);
        l0 = l0 * a0 + ps0; l1 = l1 * a1 + ps1;
        m0 = mn0; m1 = mn1;
        #pragma unroll
        for (int nt = 0; nt < 8; nt++) {
            o[nt][0] *= a0; o[nt][1] *= a0; o[nt][2] *= a1; o[nt][3] *= a1;
        }

        // O += P V  — P fragments built directly from s[] registers
        #pragma unroll
        for (int kc = 0; kc < 4; kc++) {
            uint32_t pa[4];
            pa[0] = h2u(s[2 * kc    ][0], s[2 * kc    ][1]);
            pa[1] = h2u(s[2 * kc    ][2], s[2 * kc    ][3]);
            pa[2] = h2u(s[2 * kc + 1][0], s[2 * kc + 1][1]);
            pa[3] = h2u(s[2 * kc + 1][2], s[2 * kc + 1][3]);
            uint32_t kB = kc * 32;
            uint32_t b[8][2];
            #pragma unroll
            for (int ntp = 0; ntp < 4; ntp++)
                LDSM4(b[2 * ntp][0], b[2 * ntp + 1][0],
                      b[2 * ntp][1], b[2 * ntp + 1][1],
                      vfb + ntp * (16 * ATP * 4) + kB);
            #pragma unroll
            for (int nt = 0; nt < 8; nt++)
                mma16(o[nt], pa, b[nt][0], b[nt][1]);
        }
    }

    float inv0 = 1.f / l0, inv1 = 1.f / l1;
    uint32_t* O0 = (uint32_t*)(O + baseo + (size_t)(q0 + r    ) * EMB_);
    uint32_t* O1 = (uint32_t*)(O + baseo + (size_t)(q0 + r + 8) * EMB_);
    #pragma unroll
    for (int nt = 0; nt < 8; nt++) {
        O0[nt * 4 + t4] = h2u(o[nt][0] * inv0, o[nt][1] * inv0);
        O1[nt * 4 + t4] = h2u(o[nt][2] * inv1, o[nt][3] * inv1);
    }
}

// ---------------- launch ---------------------------------------------------
extern "C" void kernel_launch(void* const* d_in, const int* in_sizes, int n_in,
                              void* d_out, int out_size)
{
    const float* x    = (const float*)d_in[0];
    const float* ln1s = (const float*)d_in[1];
    const float* ln1b = (const float*)d_in[2];
    const float* wq   = (const float*)d_in[3];
    const float* wk   = (const float*)d_in[4];
    const float* wv   = (const float*)d_in[5];
    const float* wo   = (const float*)d_in[6];
    const float* bo   = (const float*)d_in[7];
    const float* ln2s = (const float*)d_in[8];
    const float* ln2b = (const float*)d_in[9];
    const float* w1   = (const float*)d_in[10];
    const float* b1   = (const float*)d_in[11];
    const float* w2   = (const float*)d_in[12];
    const float* b2   = (const float*)d_in[13];
    float* out = (float*)d_out;

    __half *lnh, *qkvh, *ctxh, *ffhh, *wqkvh, *woh, *w1h, *w2h;
    float *x2;
    cudaGetSymbolAddress((void**)&lnh,   g_lnh);
    cudaGetSymbolAddress((void**)&qkvh,  g_qkvh);
    cudaGetSymbolAddress((void**)&ctxh,  g_ctxh);
    cudaGetSymbolAddress((void**)&ffhh,  g_ffhh);
    cudaGetSymbolAddress((void**)&x2,    g_x2);
    cudaGetSymbolAddress((void**)&wqkvh, g_wqkvh);
    cudaGetSymbolAddress((void**)&woh,   g_woh);
    cudaGetSymbolAddress((void**)&w1h,   g_w1h);
    cudaGetSymbolAddress((void**)&w2h,   g_w2h);

    cudaFuncSetAttribute(attn_mma, cudaFuncAttributeMaxDynamicSharedMemorySize, ATTN_SMEM);
    cudaFuncSetAttribute(mmagemm<0>, cudaFuncAttributeMaxDynamicSharedMemorySize, GEMM_SMEM);
    cudaFuncSetAttribute(mmagemm<1>, cudaFuncAttributeMaxDynamicSharedMemorySize, GEMM_SMEM);
    cudaFuncSetAttribute(mmagemm<2>, cudaFuncAttributeMaxDynamicSharedMemorySize, GEMM_SMEM);

    // 0) fused weight prep
    prep_all<<<6912, dim3(32, 8)>>>(wq, wk, wv, wo, w1, w2, wqkvh, woh, w1h, w2h);
    // 1) ln1 -> half
    ln_k<<<TOK, 256>>>(x, ln1s, ln1b, lnh);
    // 2) fused QKV projection (Q pre-scaled by 0.125) -> half qkv
    mmagemm<0><<<dim3(18, 64), 256, GEMM_SMEM>>>(lnh, wqkvh, nullptr, nullptr,
                                                 qkvh, EMB_, LDQKV, 24);
    // 3) causal attention (fp16 tensor cores) -> half ctx
    attn_mma<<<dim3(SEQ_ / 128, 4 * HEADS_), 256, ATTN_SMEM>>>(
        qkvh + 0, qkvh + 768, qkvh + 1536, ctxh);
    // 4) output projection + bias + residual -> fp32 x2
    mmagemm<1><<<dim3(6, 64), 256, GEMM_SMEM>>>(ctxh, woh, bo, x, x2,
                                                EMB_, EMB_, 24);
    // 5) ln2 -> half
    ln_k<<<TOK, 256>>>(x2, ln2s, ln2b, lnh);
    // 6) FF1 + bias + GELU -> half ffh
    mmagemm<2><<<dim3(24, 64), 256, GEMM_SMEM>>>(lnh, w1h, b1, nullptr, ffhh,
                                                 EMB_, FF_, 24);
    // 7) FF2 + bias + residual -> fp32 out
    mmagemm<1><<<dim3(6, 64), 256, GEMM_SMEM>>>(ffhh, w2h, b2, x2, out,
                                                FF_, EMB_, 96);
}

// round 10
// speedup vs baseline: 1.9211x; 1.0216x over previous
#include <cuda_runtime.h>
#include <cuda_fp16.h>
#include <cstdint>
#include <math.h>

#define TOK   8192
#define EMB_  768
#define FF_   3072
#define HEADS_ 12
#define SEQ_  2048
#define LDQKV 2304

// ---------------- scratch (device globals; no allocation allowed) ----------
__device__ __half g_lnh [TOK * EMB_];
__device__ __half g_qkvh[TOK * LDQKV];
__device__ __half g_ctxh[TOK * EMB_];
__device__ __half g_ffhh[(size_t)TOK * FF_];
__device__ float  g_x2  [TOK * EMB_];
__device__ __half g_wqkvh[LDQKV * EMB_];
__device__ __half g_woh  [EMB_ * EMB_];
__device__ __half g_w1h  [FF_ * EMB_];
__device__ __half g_w2h  [EMB_ * FF_];

// ---------------- helpers ---------------------------------------------------
__device__ __forceinline__ uint32_t s2u(const void* p) {
    uint32_t a;
    asm("{ .reg .u64 t; cvta.to.shared.u64 t, %1; cvt.u32.u64 %0, t; }" : "=r"(a) : "l"(p));
    return a;
}
__device__ __forceinline__ float gelu_f(float x) {
    const float c = 0.79788456080286535588f;
    float t = tanhf(c * (x + 0.044715f * x * x * x));
    return 0.5f * x * (1.f + t);
}
__device__ __forceinline__ uint32_t h2u(float a, float b) {
    __half2 h = __floats2half2_rn(a, b);
    return *reinterpret_cast<uint32_t*>(&h);
}
__device__ __forceinline__ void mma16(float c[4], const uint32_t a[4],
                                      uint32_t b0, uint32_t b1) {
    asm volatile("mma.sync.aligned.m16n8k16.row.col.f32.f16.f16.f32 "
        "{%0,%1,%2,%3}, {%4,%5,%6,%7}, {%8,%9}, {%0,%1,%2,%3};"
        : "+f"(c[0]), "+f"(c[1]), "+f"(c[2]), "+f"(c[3])
        : "r"(a[0]), "r"(a[1]), "r"(a[2]), "r"(a[3]), "r"(b0), "r"(b1));
}
#define LDSM4(d0, d1, d2, d3, addr) \
    asm volatile("ldmatrix.sync.aligned.m8n8.x4.shared.b16 {%0,%1,%2,%3}, [%4];" \
        : "=r"(d0), "=r"(d1), "=r"(d2), "=r"(d3) : "r"(addr))

#define CPA16(d, s) \
    asm volatile("cp.async.cg.shared.global [%0], [%1], 16;" :: "r"(d), "l"(s))
#define CPA_COMMIT()  asm volatile("cp.async.commit_group;" ::: "memory")
#define CPA_WAIT2()   asm volatile("cp.async.wait_group 2;" ::: "memory")
#define CPA_WAITALL() asm volatile("cp.async.wait_group 0;" ::: "memory")

// ---------------- fused weight prep: 6 transposes in one kernel ------------
__global__ void prep_all(const float* __restrict__ wq, const float* __restrict__ wk,
                         const float* __restrict__ wv, const float* __restrict__ wo,
                         const float* __restrict__ w1, const float* __restrict__ w2,
                         __half* __restrict__ wqkvh, __half* __restrict__ woh,
                         __half* __restrict__ w1h,  __half* __restrict__ w2h)
{
    __shared__ float t[32][33];
    int bid = blockIdx.x;
    const float* S; __half* D; int K, N, n0, k0;
    if (bid < 2304) {
        int m = bid / 576, tt = bid % 576;
        S = (m == 0) ? wq : (m == 1) ? wk : (m == 2) ? wv : wo;
        D = (m == 3) ? woh : wqkvh + (size_t)m * EMB_ * EMB_;
        K = EMB_; N = EMB_;
        n0 = (tt % 24) * 32; k0 = (tt / 24) * 32;
    } else if (bid < 4608) {
        int tt = bid - 2304;
        S = w1; D = w1h; K = EMB_; N = FF_;
        n0 = (tt % 96) * 32; k0 = (tt / 96) * 32;
    } else {
        int tt = bid - 4608;
        S = w2; D = w2h; K = FF_; N = EMB_;
        n0 = (tt % 24) * 32; k0 = (tt / 24) * 32;
    }
    int tx = threadIdx.x, ty = threadIdx.y;
    #pragma unroll
    for (int i = 0; i < 32; i += 8)
        t[ty + i][tx] = S[(size_t)(k0 + ty + i) * N + n0 + tx];
    __syncthreads();
    #pragma unroll
    for (int i = 0; i < 32; i += 8)
        D[(size_t)(n0 + ty + i) * K + k0 + tx] = __float2half_rn(t[tx][ty + i]);
}

// ---------------- layernorm: fp32 in -> half out ---------------------------
__global__ __launch_bounds__(256) void ln_k(const float* __restrict__ x,
                                            const float* __restrict__ sc,
                                            const float* __restrict__ sh,
                                            __half* __restrict__ out)
{
    int row = blockIdx.x;
    const float* xr = x + (size_t)row * EMB_;
    int t = threadIdx.x;
    float v0 = xr[t], v1 = xr[t + 256], v2 = xr[t + 512];

    __shared__ float red[8];
    float s = v0 + v1 + v2;
    #pragma unroll
    for (int o = 16; o; o >>= 1) s += __shfl_xor_sync(0xffffffffu, s, o);
    if ((t & 31) == 0) red[t >> 5] = s;
    __syncthreads();
    float mean = 0.f;
    #pragma unroll
    for (int i = 0; i < 8; i++) mean += red[i];
    mean *= (1.f / 768.f);

    float d0 = v0 - mean, d1 = v1 - mean, d2 = v2 - mean;
    float vs = d0 * d0 + d1 * d1 + d2 * d2;
    #pragma unroll
    for (int o = 16; o; o >>= 1) vs += __shfl_xor_sync(0xffffffffu, vs, o);
    __syncthreads();
    if ((t & 31) == 0) red[t >> 5] = vs;
    __syncthreads();
    float var = 0.f;
    #pragma unroll
    for (int i = 0; i < 8; i++) var += red[i];
    var *= (1.f / 768.f);
    float rstd = rsqrtf(var + 1e-5f);

    __half* orow = out + (size_t)row * EMB_;
    orow[t      ] = __float2half_rn(d0 * rstd * sc[t      ] + sh[t      ]);
    orow[t + 256] = __float2half_rn(d1 * rstd * sc[t + 256] + sh[t + 256]);
    orow[t + 512] = __float2half_rn(d2 * rstd * sc[t + 512] + sh[t + 512]);
}

// ---------------- fp16 mma.sync GEMM: C[M,N] = A[M,K] @ Bt[N,K]^T ----------
// CTA 128x128, 8 warps (2x4), warp tile 64x32. 4-stage cp.async, K=32/stage,
// ldmatrix fragment loads, ONE barrier per ktile.
#define PIT 20
#define B_OFF (128 * PIT)
#define STAGE_U32 (2 * 128 * PIT)
#define NSTG 4
#define GEMM_SMEM (NSTG * STAGE_U32 * 4)   // 81920 B

template<int EPI>   // 0: half out + Q-scale(qkv); 1: fp32 out +bias+res; 2: half out +bias+gelu
__global__ __launch_bounds__(256, 2) void mmagemm(const __half* __restrict__ A,
                                                  const __half* __restrict__ Bw,
                                                  const float* __restrict__ bias,
                                                  const float* __restrict__ res,
                                                  void* __restrict__ Cv,
                                                  int Kd, int ldc, int KT)
{
    extern __shared__ __align__(16) uint32_t smu[];
    int tid = threadIdx.x, lane = tid & 31, w = tid >> 5;
    int wm = w >> 2, wn = w & 3;
    int bm = blockIdx.y, bn = blockIdx.x;
    int gr = lane >> 2, t4 = lane & 3;
    int lrow = lane & 15;
    int lcol = (lane & 16) ? 4 : 0;

    float acc[4][4][4];
    #pragma unroll
    for (int i = 0; i < 4; i++)
        #pragma unroll
        for (int j = 0; j < 4; j++)
            #pragma unroll
            for (int e = 0; e < 4; e++) acc[i][j][e] = 0.f;

    auto issue = [&](int kt) {
        uint32_t* st = smu + (kt % NSTG) * STAGE_U32;
        int k0 = kt * 32;
        #pragma unroll
        for (int i = 0; i < 2; i++) {
            int chunk = tid + i * 256;
            int row = chunk >> 2, q = chunk & 3;
            CPA16(s2u(st + row * PIT + q * 4),
                  A + (size_t)(bm * 128 + row) * Kd + k0 + q * 8);
        }
        #pragma unroll
        for (int i = 0; i < 2; i++) {
            int chunk = tid + i * 256;
            int n = chunk >> 2, q = chunk & 3;
            CPA16(s2u(st + B_OFF + n * PIT + q * 4),
                  Bw + (size_t)(bn * 128 + n) * Kd + k0 + q * 8);
        }
    };

    issue(0); CPA_COMMIT();
    issue(1); CPA_COMMIT();
    issue(2); CPA_COMMIT();

    for (int kt = 0; kt < KT; kt++) {
        CPA_WAIT2();          // group kt complete
        __syncthreads();      // + all warps done with compute(kt-1)
        if (kt + 3 < KT) issue(kt + 3);   // writes stage (kt-1)%4 — safe
        CPA_COMMIT();

        const uint32_t* As = smu + (kt % NSTG) * STAGE_U32;
        uint32_t a_base = s2u(As + (wm * 64 + lrow) * PIT + lcol);
        uint32_t b_base = s2u(As + B_OFF + (wn * 32 + lrow) * PIT + lcol);

        #pragma unroll
        for (int kc = 0; kc < 2; kc++) {
            uint32_t kB = kc * 32;
            uint32_t a[4][4];
            #pragma unroll
            for (int mt = 0; mt < 4; mt++)
                LDSM4(a[mt][0], a[mt][1], a[mt][2], a[mt][3],
                      a_base + mt * (16 * PIT * 4) + kB);
            uint32_t b[4][2];
            #pragma unroll
            for (int ntp = 0; ntp < 2; ntp++)
                LDSM4(b[2 * ntp][0], b[2 * ntp + 1][0],
                      b[2 * ntp][1], b[2 * ntp + 1][1],
                      b_base + ntp * (16 * PIT * 4) + kB);
            #pragma unroll
            for (int mt = 0; mt < 4; mt++)
                #pragma unroll
                for (int nt = 0; nt < 4; nt++)
                    mma16(acc[mt][nt], a[mt], b[nt][0], b[nt][1]);
        }
    }

    // ---- epilogue ----
    float scale = 1.f;
    if (EPI == 0) scale = (bn * 128 < 768) ? 0.125f : 1.f;
    float bv[4][2];
    if (EPI >= 1) {
        #pragma unroll
        for (int nt = 0; nt < 4; nt++) {
            int col = bn * 128 + wn * 32 + nt * 8 + t4 * 2;
            bv[nt][0] = bias[col]; bv[nt][1] = bias[col + 1];
        }
    }
    #pragma unroll
    for (int mt = 0; mt < 4; mt++) {
        #pragma unroll
        for (int rr = 0; rr < 2; rr++) {
            int row = bm * 128 + wm * 64 + mt * 16 + gr + rr * 8;
            size_t off = (size_t)row * ldc + bn * 128 + wn * 32 + t4 * 2;
            #pragma unroll
            for (int nt = 0; nt < 4; nt++) {
                float v0 = acc[mt][nt][rr * 2 + 0];
                float v1 = acc[mt][nt][rr * 2 + 1];
                if (EPI == 0) { v0 *= scale; v1 *= scale; }
                if (EPI >= 1) { v0 += bv[nt][0]; v1 += bv[nt][1]; }
                if (EPI == 2) { v0 = gelu_f(v0); v1 = gelu_f(v1); }
                if (EPI == 1) {
                    float2 r2 = *(const float2*)&res[off + nt * 8];
                    *(float2*)&((float*)Cv)[off + nt * 8] =
                        make_float2(v0 + r2.x, v1 + r2.y);
                } else {
                    *reinterpret_cast<uint32_t*>((__half*)Cv + off + nt * 8) = h2u(v0, v1);
                }
            }
        }
    }
}

// ---------------- causal flash attention, fp16 mma.sync --------------------
// BQ=128, BK=64, D=64. Double-buffered K/V (cp.async / prefetched LDG),
// one barrier per tile, LPT block order (heavy q-tiles first).
#define ATP 36
#define KBUF(s) (smu + (s) * 2304)
#define VBUF(s) (smu + 4608 + (s) * 2304)
#define ATTN_SMEM (9216 * 4)   // 36864 B

__global__ __launch_bounds__(256, 2) void attn_mma(const __half* __restrict__ Q,
                                                   const __half* __restrict__ K,
                                                   const __half* __restrict__ V,
                                                   __half* __restrict__ O)
{
    extern __shared__ __align__(16) uint32_t smu[];

    int tid = threadIdx.x, lane = tid & 31, w = tid >> 5;
    int gr = lane >> 2, t4 = lane & 3;
    int lrow = lane & 15;
    int lcol = (lane & 16) ? 4 : 0;
    int bh = blockIdx.y, bb = bh / HEADS_, h = bh % HEADS_;
    int qb = gridDim.x - 1 - blockIdx.x;       // LPT: heavy tiles first
    int q0 = qb * 128;
    size_t baseq = (size_t)bb * SEQ_ * LDQKV + (size_t)h * 64;
    size_t baseo = (size_t)bb * SEQ_ * EMB_  + (size_t)h * 64;
    int r = w * 16 + gr;
    int kp  = (lane >> 2) | ((w & 3) << 3);
    int d2b = (lane & 3)  | ((w >> 2) << 2);

    // stage Q (pre-scaled) into smem, extract frags to regs
    for (int i = tid; i < 1024; i += 256) {
        int row = i >> 3, q = i & 7;
        CPA16(s2u(smu + row * ATP + q * 4),
              Q + baseq + (size_t)(q0 + row) * LDQKV + q * 8);
    }
    CPA_COMMIT(); CPA_WAITALL();
    __syncthreads();
    uint32_t qf[4][4];
    {
        uint32_t qbase = s2u(smu + (w * 16 + lrow) * ATP + lcol);
        #pragma unroll
        for (int kc = 0; kc < 4; kc++)
            LDSM4(qf[kc][0], qf[kc][1], qf[kc][2], qf[kc][3], qbase + kc * 32);
    }
    __syncthreads();          // Q reads done; K/V buffers may overwrite

    auto issueK = [&](int jj, uint32_t* kb) {
        for (int i = tid; i < 512; i += 256) {
            int row = i >> 3, q = i & 7;
            CPA16(s2u(kb + row * ATP + q * 4),
                  K + baseq + (size_t)(jj * 64 + row) * LDQKV + q * 8);
        }
        CPA_COMMIT();
    };

    float m0 = -1e30f, m1 = -1e30f, l0 = 0.f, l1 = 0.f;
    float o[8][4];
    #pragma unroll
    for (int nt = 0; nt < 8; nt++)
        #pragma unroll
        for (int e = 0; e < 4; e++) o[nt][e] = 0.f;

    int jmaxt = 2 * qb + 1;
    int qlo = q0 + r;

    // prologue: tile 0 into buffer 0
    issueK(0, KBUF(0));
    {
        const uint32_t* vg0 = (const uint32_t*)(V + baseq + (size_t)(2 * kp) * LDQKV);
        const uint32_t* vg1 = vg0 + LDQKV / 2;
        #pragma unroll
        for (int it = 0; it < 4; it++) {
            int d2 = d2b + it * 8;
            uint32_t v0 = vg0[d2], v1 = vg1[d2];
            VBUF(0)[(2 * d2    ) * ATP + kp] = __byte_perm(v0, v1, 0x5410);
            VBUF(0)[(2 * d2 + 1) * ATP + kp] = __byte_perm(v0, v1, 0x7632);
        }
    }
    CPA_WAITALL();
    __syncthreads();

    for (int j = 0; j <= jmaxt; j++) {
        int buf = j & 1, nb = buf ^ 1;
        // prefetch next tile: K via cp.async, V LDGs into regs (STS after compute)
        uint32_t pv0[4], pv1[4];
        if (j < jmaxt) {
            issueK(j + 1, KBUF(nb));
            const uint32_t* vg0 = (const uint32_t*)(V + baseq + (size_t)((j + 1) * 64 + 2 * kp) * LDQKV);
            const uint32_t* vg1 = vg0 + LDQKV / 2;
            #pragma unroll
            for (int it = 0; it < 4; it++) {
                int d2 = d2b + it * 8;
                pv0[it] = vg0[d2]; pv1[it] = vg1[d2];
            }
        }

        uint32_t kfb = s2u(KBUF(buf) + lrow * ATP + lcol);
        uint32_t vfb = s2u(VBUF(buf) + lrow * ATP + lcol);

        // S = Q K^T
        float s[8][4];
        #pragma unroll
        for (int nt = 0; nt < 8; nt++)
            #pragma unroll
            for (int e = 0; e < 4; e++) s[nt][e] = 0.f;
        #pragma unroll
        for (int kc = 0; kc < 4; kc++) {
            uint32_t kB = kc * 32;
            uint32_t b[8][2];
            #pragma unroll
            for (int ntp = 0; ntp < 4; ntp++)
                LDSM4(b[2 * ntp][0], b[2 * ntp + 1][0],
                      b[2 * ntp][1], b[2 * ntp + 1][1],
                      kfb + ntp * (16 * ATP * 4) + kB);
            #pragma unroll
            for (int nt = 0; nt < 8; nt++)
                mma16(s[nt], qf[kc], b[nt][0], b[nt][1]);
        }

        // causal mask
        if (j * 64 + 63 > q0 + w * 16) {
            #pragma unroll
            for (int nt = 0; nt < 8; nt++) {
                int c0 = j * 64 + nt * 8 + 2 * t4;
                if (c0     > qlo    ) s[nt][0] = -1e30f;
                if (c0 + 1 > qlo    ) s[nt][1] = -1e30f;
                if (c0     > qlo + 8) s[nt][2] = -1e30f;
                if (c0 + 1 > qlo + 8) s[nt][3] = -1e30f;
            }
        }

        // online softmax
        float mt0 = -1e30f, mt1 = -1e30f;
        #pragma unroll
        for (int nt = 0; nt < 8; nt++) {
            mt0 = fmaxf(mt0, fmaxf(s[nt][0], s[nt][1]));
            mt1 = fmaxf(mt1, fmaxf(s[nt][2], s[nt][3]));
        }
        mt0 = fmaxf(mt0, __shfl_xor_sync(0xffffffffu, mt0, 1));
        mt0 = fmaxf(mt0, __shfl_xor_sync(0xffffffffu, mt0, 2));
        mt1 = fmaxf(mt1, __shfl_xor_sync(0xffffffffu, mt1, 1));
        mt1 = fmaxf(mt1, __shfl_xor_sync(0xffffffffu, mt1, 2));
        float mn0 = fmaxf(m0, mt0), mn1 = fmaxf(m1, mt1);
        float a0 = __expf(m0 - mn0), a1 = __expf(m1 - mn1);
        float ps0 = 0.f, ps1 = 0.f;
        #pragma unroll
        for (int nt = 0; nt < 8; nt++) {
            s[nt][0] = __expf(s[nt][0] - mn0); ps0 += s[nt][0];
            s[nt][1] = __expf(s[nt][1] - mn0); ps0 += s[nt][1];
            s[nt][2] = __expf(s[nt][2] - mn1); ps1 += s[nt][2];
            s[nt][3] = __expf(s[nt][3] - mn1); ps1 += s[nt][3];
        }
        ps0 += __shfl_xor_sync(0xffffffffu, ps0, 1);
        ps0 += __shfl_xor_sync(0xffffffffu, ps0, 2);
        ps1 += __shfl_xor_sync(0xffffffffu, ps1, 1);
        ps1 += __shfl_xor_sync(0xffffffffu, ps1, 2);
        l0 = l0 * a0 + ps0; l1 = l1 * a1 + ps1;
        m0 = mn0; m1 = mn1;
        #pragma unroll
        for (int nt = 0; nt < 8; nt++) {
            o[nt][0] *= a0; o[nt][1] *= a0; o[nt][2] *= a1; o[nt][3] *= a1;
        }

        // O += P V  (P fragments direct from s[] registers)
        #pragma unroll
        for (int kc = 0; kc < 4; kc++) {
            uint32_t pa[4];
            pa[0] = h2u(s[2 * kc    ][0], s[2 * kc    ][1]);
            pa[1] = h2u(s[2 * kc    ][2], s[2 * kc    ][3]);
            pa[2] = h2u(s[2 * kc + 1][0], s[2 * kc + 1][1]);
            pa[3] = h2u(s[2 * kc + 1][2], s[2 * kc + 1][3]);
            uint32_t kB = kc * 32;
            uint32_t b[8][2];
            #pragma unroll
            for (int ntp = 0; ntp < 4; ntp++)
                LDSM4(b[2 * ntp][0], b[2 * ntp + 1][0],
                      b[2 * ntp][1], b[2 * ntp + 1][1],
                      vfb + ntp * (16 * ATP * 4) + kB);
            #pragma unroll
            for (int nt = 0; nt < 8; nt++)
                mma16(o[nt], pa, b[nt][0], b[nt][1]);
        }

        // store prefetched V(j+1) into the free buffer, then one barrier
        if (j < jmaxt) {
            #pragma unroll
            for (int it = 0; it < 4; it++) {
                int d2 = d2b + it * 8;
                VBUF(nb)[(2 * d2    ) * ATP + kp] = __byte_perm(pv0[it], pv1[it], 0x5410);
                VBUF(nb)[(2 * d2 + 1) * ATP + kp] = __byte_perm(pv0[it], pv1[it], 0x7632);
            }
        }
        CPA_WAITALL();
        __syncthreads();
    }

    float inv0 = 1.f / l0, inv1 = 1.f / l1;
    uint32_t* O0 = (uint32_t*)(O + baseo + (size_t)(q0 + r    ) * EMB_);
    uint32_t* O1 = (uint32_t*)(O + baseo + (size_t)(q0 + r + 8) * EMB_);
    #pragma unroll
    for (int nt = 0; nt < 8; nt++) {
        O0[nt * 4 + t4] = h2u(o[nt][0] * inv0, o[nt][1] * inv0);
        O1[nt * 4 + t4] = h2u(o[nt][2] * inv1, o[nt][3] * inv1);
    }
}

// ---------------- launch ---------------------------------------------------
extern "C" void kernel_launch(void* const* d_in, const int* in_sizes, int n_in,
                              void* d_out, int out_size)
{
    const float* x    = (const float*)d_in[0];
    const float* ln1s = (const float*)d_in[1];
    const float* ln1b = (const float*)d_in[2];
    const float* wq   = (const float*)d_in[3];
    const float* wk   = (const float*)d_in[4];
    const float* wv   = (const float*)d_in[5];
    const float* wo   = (const float*)d_in[6];
    const float* bo   = (const float*)d_in[7];
    const float* ln2s = (const float*)d_in[8];
    const float* ln2b = (const float*)d_in[9];
    const float* w1   = (const float*)d_in[10];
    const float* b1   = (const float*)d_in[11];
    const float* w2   = (const float*)d_in[12];
    const float* b2   = (const float*)d_in[13];
    float* out = (float*)d_out;

    __half *lnh, *qkvh, *ctxh, *ffhh, *wqkvh, *woh, *w1h, *w2h;
    float *x2;
    cudaGetSymbolAddress((void**)&lnh,   g_lnh);
    cudaGetSymbolAddress((void**)&qkvh,  g_qkvh);
    cudaGetSymbolAddress((void**)&ctxh,  g_ctxh);
    cudaGetSymbolAddress((void**)&ffhh,  g_ffhh);
    cudaGetSymbolAddress((void**)&x2,    g_x2);
    cudaGetSymbolAddress((void**)&wqkvh, g_wqkvh);
    cudaGetSymbolAddress((void**)&woh,   g_woh);
    cudaGetSymbolAddress((void**)&w1h,   g_w1h);
    cudaGetSymbolAddress((void**)&w2h,   g_w2h);

    cudaFuncSetAttribute(attn_mma, cudaFuncAttributeMaxDynamicSharedMemorySize, ATTN_SMEM);
    cudaFuncSetAttribute(mmagemm<0>, cudaFuncAttributeMaxDynamicSharedMemorySize, GEMM_SMEM);
    cudaFuncSetAttribute(mmagemm<1>, cudaFuncAttributeMaxDynamicSharedMemorySize, GEMM_SMEM);
    cudaFuncSetAttribute(mmagemm<2>, cudaFuncAttributeMaxDynamicSharedMemorySize, GEMM_SMEM);

    // 0) fused weight prep
    prep_all<<<6912, dim3(32, 8)>>>(wq, wk, wv, wo, w1, w2, wqkvh, woh, w1h, w2h);
    // 1) ln1 -> half
    ln_k<<<TOK, 256>>>(x, ln1s, ln1b, lnh);
    // 2) fused QKV projection (Q pre-scaled by 0.125) -> half qkv
    mmagemm<0><<<dim3(18, 64), 256, GEMM_SMEM>>>(lnh, wqkvh, nullptr, nullptr,
                                                 qkvh, EMB_, LDQKV, 24);
    // 3) causal attention -> half ctx
    attn_mma<<<dim3(SEQ_ / 128, 4 * HEADS_), 256, ATTN_SMEM>>>(
        qkvh + 0, qkvh + 768, qkvh + 1536, ctxh);
    // 4) output projection + bias + residual -> fp32 x2
    mmagemm<1><<<dim3(6, 64), 256, GEMM_SMEM>>>(ctxh, woh, bo, x, x2,
                                                EMB_, EMB_, 24);
    // 5) ln2 -> half
    ln_k<<<TOK, 256>>>(x2, ln2s, ln2b, lnh);
    // 6) FF1 + bias + GELU -> half ffh
    mmagemm<2><<<dim3(24, 64), 256, GEMM_SMEM>>>(lnh, w1h, b1, nullptr, ffhh,
                                                 EMB_, FF_, 24);
    // 7) FF2 + bias + residual -> fp32 out
    mmagemm<1><<<dim3(6, 64), 256, GEMM_SMEM>>>(ffhh, w2h, b2, x2, out,
                                                FF_, EMB_, 96);
}

// round 11
// speedup vs baseline: 2.1317x; 1.1096x over previous
#include <cuda_runtime.h>
#include <cuda_fp16.h>
#include <cstdint>
#include <math.h>

#define TOK   8192
#define EMB_  768
#define FF_   3072
#define HEADS_ 12
#define SEQ_  2048
#define LDQKV 2304

// ---------------- scratch (device globals; no allocation allowed) ----------
__device__ __half g_lnh [TOK * EMB_];
__device__ __half g_qkvh[TOK * LDQKV];
__device__ __half g_ctxh[TOK * EMB_];
__device__ __half g_ffhh[(size_t)TOK * FF_];
__device__ float  g_x2  [TOK * EMB_];
__device__ __half g_wqkvh[LDQKV * EMB_];
__device__ __half g_woh  [EMB_ * EMB_];
__device__ __half g_w1h  [FF_ * EMB_];
__device__ __half g_w2h  [EMB_ * FF_];

// ---------------- helpers ---------------------------------------------------
__device__ __forceinline__ uint32_t s2u(const void* p) {
    uint32_t a;
    asm("{ .reg .u64 t; cvta.to.shared.u64 t, %1; cvt.u32.u64 %0, t; }" : "=r"(a) : "l"(p));
    return a;
}
__device__ __forceinline__ float gelu_f(float x) {
    const float c = 0.79788456080286535588f;
    float t = tanhf(c * (x + 0.044715f * x * x * x));
    return 0.5f * x * (1.f + t);
}
__device__ __forceinline__ uint32_t h2u(float a, float b) {
    __half2 h = __floats2half2_rn(a, b);
    return *reinterpret_cast<uint32_t*>(&h);
}
__device__ __forceinline__ void mma16(float c[4], const uint32_t a[4],
                                      uint32_t b0, uint32_t b1) {
    asm volatile("mma.sync.aligned.m16n8k16.row.col.f32.f16.f16.f32 "
        "{%0,%1,%2,%3}, {%4,%5,%6,%7}, {%8,%9}, {%0,%1,%2,%3};"
        : "+f"(c[0]), "+f"(c[1]), "+f"(c[2]), "+f"(c[3])
        : "r"(a[0]), "r"(a[1]), "r"(a[2]), "r"(a[3]), "r"(b0), "r"(b1));
}
#define LDSM4(d0, d1, d2, d3, addr) \
    asm volatile("ldmatrix.sync.aligned.m8n8.x4.shared.b16 {%0,%1,%2,%3}, [%4];" \
        : "=r"(d0), "=r"(d1), "=r"(d2), "=r"(d3) : "r"(addr))

#define CPA16(d, s) \
    asm volatile("cp.async.cg.shared.global [%0], [%1], 16;" :: "r"(d), "l"(s))
#define CPA_COMMIT()  asm volatile("cp.async.commit_group;" ::: "memory")
#define CPA_WAIT1()   asm volatile("cp.async.wait_group 1;" ::: "memory")
#define CPA_WAITALL() asm volatile("cp.async.wait_group 0;" ::: "memory")

// ---------------- fused weight prep: 6 transposes in one kernel ------------
__global__ void prep_all(const float* __restrict__ wq, const float* __restrict__ wk,
                         const float* __restrict__ wv, const float* __restrict__ wo,
                         const float* __restrict__ w1, const float* __restrict__ w2,
                         __half* __restrict__ wqkvh, __half* __restrict__ woh,
                         __half* __restrict__ w1h,  __half* __restrict__ w2h)
{
    __shared__ float t[32][33];
    int bid = blockIdx.x;
    const float* S; __half* D; int K, N, n0, k0;
    if (bid < 2304) {
        int m = bid / 576, tt = bid % 576;
        S = (m == 0) ? wq : (m == 1) ? wk : (m == 2) ? wv : wo;
        D = (m == 3) ? woh : wqkvh + (size_t)m * EMB_ * EMB_;
        K = EMB_; N = EMB_;
        n0 = (tt % 24) * 32; k0 = (tt / 24) * 32;
    } else if (bid < 4608) {
        int tt = bid - 2304;
        S = w1; D = w1h; K = EMB_; N = FF_;
        n0 = (tt % 96) * 32; k0 = (tt / 96) * 32;
    } else {
        int tt = bid - 4608;
        S = w2; D = w2h; K = FF_; N = EMB_;
        n0 = (tt % 24) * 32; k0 = (tt / 24) * 32;
    }
    int tx = threadIdx.x, ty = threadIdx.y;
    #pragma unroll
    for (int i = 0; i < 32; i += 8)
        t[ty + i][tx] = S[(size_t)(k0 + ty + i) * N + n0 + tx];
    __syncthreads();
    #pragma unroll
    for (int i = 0; i < 32; i += 8)
        D[(size_t)(n0 + ty + i) * K + k0 + tx] = __float2half_rn(t[tx][ty + i]);
}

// ---------------- layernorm: fp32 in -> half out ---------------------------
__global__ __launch_bounds__(256) void ln_k(const float* __restrict__ x,
                                            const float* __restrict__ sc,
                                            const float* __restrict__ sh,
                                            __half* __restrict__ out)
{
    int row = blockIdx.x;
    const float* xr = x + (size_t)row * EMB_;
    int t = threadIdx.x;
    float v0 = xr[t], v1 = xr[t + 256], v2 = xr[t + 512];

    __shared__ float red[8];
    float s = v0 + v1 + v2;
    #pragma unroll
    for (int o = 16; o; o >>= 1) s += __shfl_xor_sync(0xffffffffu, s, o);
    if ((t & 31) == 0) red[t >> 5] = s;
    __syncthreads();
    float mean = 0.f;
    #pragma unroll
    for (int i = 0; i < 8; i++) mean += red[i];
    mean *= (1.f / 768.f);

    float d0 = v0 - mean, d1 = v1 - mean, d2 = v2 - mean;
    float vs = d0 * d0 + d1 * d1 + d2 * d2;
    #pragma unroll
    for (int o = 16; o; o >>= 1) vs += __shfl_xor_sync(0xffffffffu, vs, o);
    __syncthreads();
    if ((t & 31) == 0) red[t >> 5] = vs;
    __syncthreads();
    float var = 0.f;
    #pragma unroll
    for (int i = 0; i < 8; i++) var += red[i];
    var *= (1.f / 768.f);
    float rstd = rsqrtf(var + 1e-5f);

    __half* orow = out + (size_t)row * EMB_;
    orow[t      ] = __float2half_rn(d0 * rstd * sc[t      ] + sh[t      ]);
    orow[t + 256] = __float2half_rn(d1 * rstd * sc[t + 256] + sh[t + 256]);
    orow[t + 512] = __float2half_rn(d2 * rstd * sc[t + 512] + sh[t + 512]);
}

// ---------------- fp16 mma.sync GEMM: C[M,N] = A[M,K] @ Bt[N,K]^T ----------
// CTA 128x128, 8 warps (2x4), warp tile 64x32. 3-stage cp.async, K=64/stage,
// ldmatrix fragment loads, ONE barrier per 64-K ktile.
#define PIT 36
#define B_OFF (128 * PIT)
#define STAGE_U32 (2 * 128 * PIT)
#define NSTG 3
#define GEMM_SMEM (NSTG * STAGE_U32 * 4)   // 110592 B

template<int EPI>   // 0: half out + Q-scale(qkv); 1: fp32 out +bias+res; 2: half out +bias+gelu
__global__ __launch_bounds__(256, 2) void mmagemm(const __half* __restrict__ A,
                                                  const __half* __restrict__ Bw,
                                                  const float* __restrict__ bias,
                                                  const float* __restrict__ res,
                                                  void* __restrict__ Cv,
                                                  int Kd, int ldc, int KT)
{
    extern __shared__ __align__(16) uint32_t smu[];
    int tid = threadIdx.x, lane = tid & 31, w = tid >> 5;
    int wm = w >> 2, wn = w & 3;
    int bm = blockIdx.y, bn = blockIdx.x;
    int gr = lane >> 2, t4 = lane & 3;
    int lrow = lane & 15;
    int lcol = (lane & 16) ? 4 : 0;

    float acc[4][4][4];
    #pragma unroll
    for (int i = 0; i < 4; i++)
        #pragma unroll
        for (int j = 0; j < 4; j++)
            #pragma unroll
            for (int e = 0; e < 4; e++) acc[i][j][e] = 0.f;

    auto issue = [&](int kt) {
        uint32_t* st = smu + (kt % NSTG) * STAGE_U32;
        int k0 = kt * 64;
        #pragma unroll
        for (int i = 0; i < 4; i++) {        // A: 128 rows x 8 chunks = 1024
            int chunk = tid + i * 256;
            int row = chunk >> 3, q = chunk & 7;
            CPA16(s2u(st + row * PIT + q * 4),
                  A + (size_t)(bm * 128 + row) * Kd + k0 + q * 8);
        }
        #pragma unroll
        for (int i = 0; i < 4; i++) {        // B: 128 n-rows x 8 chunks
            int chunk = tid + i * 256;
            int n = chunk >> 3, q = chunk & 7;
            CPA16(s2u(st + B_OFF + n * PIT + q * 4),
                  Bw + (size_t)(bn * 128 + n) * Kd + k0 + q * 8);
        }
    };

    issue(0); CPA_COMMIT();
    issue(1); CPA_COMMIT();

    for (int kt = 0; kt < KT; kt++) {
        CPA_WAIT1();          // group kt complete (pending: kt, kt+1)
        __syncthreads();      // all warps done with stage (kt-1)%3 reads
        if (kt + 2 < KT) issue(kt + 2);   // writes stage (kt+2)%3 = (kt-1)%3 — safe
        CPA_COMMIT();

        const uint32_t* As = smu + (kt % NSTG) * STAGE_U32;
        uint32_t a_base = s2u(As + (wm * 64 + lrow) * PIT + lcol);
        uint32_t b_base = s2u(As + B_OFF + (wn * 32 + lrow) * PIT + lcol);

        #pragma unroll
        for (int kc = 0; kc < 4; kc++) {
            uint32_t kB = kc * 32;
            uint32_t a[4][4];
            #pragma unroll
            for (int mt = 0; mt < 4; mt++)
                LDSM4(a[mt][0], a[mt][1], a[mt][2], a[mt][3],
                      a_base + mt * (16 * PIT * 4) + kB);
            uint32_t b[4][2];
            #pragma unroll
            for (int ntp = 0; ntp < 2; ntp++)
                LDSM4(b[2 * ntp][0], b[2 * ntp + 1][0],
                      b[2 * ntp][1], b[2 * ntp + 1][1],
                      b_base + ntp * (16 * PIT * 4) + kB);
            #pragma unroll
            for (int mt = 0; mt < 4; mt++)
                #pragma unroll
                for (int nt = 0; nt < 4; nt++)
                    mma16(acc[mt][nt], a[mt], b[nt][0], b[nt][1]);
        }
    }

    // ---- epilogue ----
    float scale = 1.f;
    if (EPI == 0) scale = (bn * 128 < 768) ? 0.1803368801111204f : 1.f;  // 0.125*log2(e)
    float bv[4][2];
    if (EPI >= 1) {
        #pragma unroll
        for (int nt = 0; nt < 4; nt++) {
            int col = bn * 128 + wn * 32 + nt * 8 + t4 * 2;
            bv[nt][0] = bias[col]; bv[nt][1] = bias[col + 1];
        }
    }
    #pragma unroll
    for (int mt = 0; mt < 4; mt++) {
        #pragma unroll
        for (int rr = 0; rr < 2; rr++) {
            int row = bm * 128 + wm * 64 + mt * 16 + gr + rr * 8;
            size_t off = (size_t)row * ldc + bn * 128 + wn * 32 + t4 * 2;
            #pragma unroll
            for (int nt = 0; nt < 4; nt++) {
                float v0 = acc[mt][nt][rr * 2 + 0];
                float v1 = acc[mt][nt][rr * 2 + 1];
                if (EPI == 0) { v0 *= scale; v1 *= scale; }
                if (EPI >= 1) { v0 += bv[nt][0]; v1 += bv[nt][1]; }
                if (EPI == 2) { v0 = gelu_f(v0); v1 = gelu_f(v1); }
                if (EPI == 1) {
                    float2 r2 = *(const float2*)&res[off + nt * 8];
                    *(float2*)&((float*)Cv)[off + nt * 8] =
                        make_float2(v0 + r2.x, v1 + r2.y);
                } else {
                    *reinterpret_cast<uint32_t*>((__half*)Cv + off + nt * 8) = h2u(v0, v1);
                }
            }
        }
    }
}

// ---------------- causal flash attention, fp16 mma.sync --------------------
// BQ=128, BK=64, D=64. Double-buffered K/V, one barrier per tile, LPT order.
// Q pre-scaled by 0.125*log2(e) -> softmax in base-2 (exp2f, no mul).
#define ATP 36
#define KBUF(s) (smu + (s) * 2304)
#define VBUF(s) (smu + 4608 + (s) * 2304)
#define ATTN_SMEM (9216 * 4)   // 36864 B

__global__ __launch_bounds__(256, 2) void attn_mma(const __half* __restrict__ Q,
                                                   const __half* __restrict__ K,
                                                   const __half* __restrict__ V,
                                                   __half* __restrict__ O)
{
    extern __shared__ __align__(16) uint32_t smu[];

    int tid = threadIdx.x, lane = tid & 31, w = tid >> 5;
    int gr = lane >> 2, t4 = lane & 3;
    int lrow = lane & 15;
    int lcol = (lane & 16) ? 4 : 0;
    int bh = blockIdx.y, bb = bh / HEADS_, h = bh % HEADS_;
    int qb = gridDim.x - 1 - blockIdx.x;       // LPT: heavy tiles first
    int q0 = qb * 128;
    size_t baseq = (size_t)bb * SEQ_ * LDQKV + (size_t)h * 64;
    size_t baseo = (size_t)bb * SEQ_ * EMB_  + (size_t)h * 64;
    int r = w * 16 + gr;
    int kp  = (lane >> 2) | ((w & 3) << 3);
    int d2b = (lane & 3)  | ((w >> 2) << 2);

    for (int i = tid; i < 1024; i += 256) {
        int row = i >> 3, q = i & 7;
        CPA16(s2u(smu + row * ATP + q * 4),
              Q + baseq + (size_t)(q0 + row) * LDQKV + q * 8);
    }
    CPA_COMMIT(); CPA_WAITALL();
    __syncthreads();
    uint32_t qf[4][4];
    {
        uint32_t qbase = s2u(smu + (w * 16 + lrow) * ATP + lcol);
        #pragma unroll
        for (int kc = 0; kc < 4; kc++)
            LDSM4(qf[kc][0], qf[kc][1], qf[kc][2], qf[kc][3], qbase + kc * 32);
    }
    __syncthreads();

    auto issueK = [&](int jj, uint32_t* kb) {
        for (int i = tid; i < 512; i += 256) {
            int row = i >> 3, q = i & 7;
            CPA16(s2u(kb + row * ATP + q * 4),
                  K + baseq + (size_t)(jj * 64 + row) * LDQKV + q * 8);
        }
        CPA_COMMIT();
    };

    float m0 = -1e30f, m1 = -1e30f, l0 = 0.f, l1 = 0.f;
    float o[8][4];
    #pragma unroll
    for (int nt = 0; nt < 8; nt++)
        #pragma unroll
        for (int e = 0; e < 4; e++) o[nt][e] = 0.f;

    int jmaxt = 2 * qb + 1;
    int qlo = q0 + r;

    issueK(0, KBUF(0));
    {
        const uint32_t* vg0 = (const uint32_t*)(V + baseq + (size_t)(2 * kp) * LDQKV);
        const uint32_t* vg1 = vg0 + LDQKV / 2;
        #pragma unroll
        for (int it = 0; it < 4; it++) {
            int d2 = d2b + it * 8;
            uint32_t v0 = vg0[d2], v1 = vg1[d2];
            VBUF(0)[(2 * d2    ) * ATP + kp] = __byte_perm(v0, v1, 0x5410);
            VBUF(0)[(2 * d2 + 1) * ATP + kp] = __byte_perm(v0, v1, 0x7632);
        }
    }
    CPA_WAITALL();
    __syncthreads();

    for (int j = 0; j <= jmaxt; j++) {
        int buf = j & 1, nb = buf ^ 1;
        uint32_t pv0[4], pv1[4];
        if (j < jmaxt) {
            issueK(j + 1, KBUF(nb));
            const uint32_t* vg0 = (const uint32_t*)(V + baseq + (size_t)((j + 1) * 64 + 2 * kp) * LDQKV);
            const uint32_t* vg1 = vg0 + LDQKV / 2;
            #pragma unroll
            for (int it = 0; it < 4; it++) {
                int d2 = d2b + it * 8;
                pv0[it] = vg0[d2]; pv1[it] = vg1[d2];
            }
        }

        uint32_t kfb = s2u(KBUF(buf) + lrow * ATP + lcol);
        uint32_t vfb = s2u(VBUF(buf) + lrow * ATP + lcol);

        // S = Q K^T  (S is in base-2 log units: s = score * log2e)
        float s[8][4];
        #pragma unroll
        for (int nt = 0; nt < 8; nt++)
            #pragma unroll
            for (int e = 0; e < 4; e++) s[nt][e] = 0.f;
        #pragma unroll
        for (int kc = 0; kc < 4; kc++) {
            uint32_t kB = kc * 32;
            uint32_t b[8][2];
            #pragma unroll
            for (int ntp = 0; ntp < 4; ntp++)
                LDSM4(b[2 * ntp][0], b[2 * ntp + 1][0],
                      b[2 * ntp][1], b[2 * ntp + 1][1],
                      kfb + ntp * (16 * ATP * 4) + kB);
            #pragma unroll
            for (int nt = 0; nt < 8; nt++)
                mma16(s[nt], qf[kc], b[nt][0], b[nt][1]);
        }

        if (j * 64 + 63 > q0 + w * 16) {
            #pragma unroll
            for (int nt = 0; nt < 8; nt++) {
                int c0 = j * 64 + nt * 8 + 2 * t4;
                if (c0     > qlo    ) s[nt][0] = -1e30f;
                if (c0 + 1 > qlo    ) s[nt][1] = -1e30f;
                if (c0     > qlo + 8) s[nt][2] = -1e30f;
                if (c0 + 1 > qlo + 8) s[nt][3] = -1e30f;
            }
        }

        float mt0 = -1e30f, mt1 = -1e30f;
        #pragma unroll
        for (int nt = 0; nt < 8; nt++) {
            mt0 = fmaxf(mt0, fmaxf(s[nt][0], s[nt][1]));
            mt1 = fmaxf(mt1, fmaxf(s[nt][2], s[nt][3]));
        }
        mt0 = fmaxf(mt0, __shfl_xor_sync(0xffffffffu, mt0, 1));
        mt0 = fmaxf(mt0, __shfl_xor_sync(0xffffffffu, mt0, 2));
        mt1 = fmaxf(mt1, __shfl_xor_sync(0xffffffffu, mt1, 1));
        mt1 = fmaxf(mt1, __shfl_xor_sync(0xffffffffu, mt1, 2));
        float mn0 = fmaxf(m0, mt0), mn1 = fmaxf(m1, mt1);
        float a0 = exp2f(m0 - mn0), a1 = exp2f(m1 - mn1);
        float ps0 = 0.f, ps1 = 0.f;
        #pragma unroll
        for (int nt = 0; nt < 8; nt++) {
            s[nt][0] = exp2f(s[nt][0] - mn0); ps0 += s[nt][0];
            s[nt][1] = exp2f(s[nt][1] - mn0); ps0 += s[nt][1];
            s[nt][2] = exp2f(s[nt][2] - mn1); ps1 += s[nt][2];
            s[nt][3] = exp2f(s[nt][3] - mn1); ps1 += s[nt][3];
        }
        ps0 += __shfl_xor_sync(0xffffffffu, ps0, 1);
        ps0 += __shfl_xor_sync(0xffffffffu, ps0, 2);
        ps1 += __shfl_xor_sync(0xffffffffu, ps1, 1);
        ps1 += __shfl_xor_sync(0xffffffffu, ps1, 2);
        l0 = l0 * a0 + ps0; l1 = l1 * a1 + ps1;
        m0 = mn0; m1 = mn1;
        #pragma unroll
        for (int nt = 0; nt < 8; nt++) {
            o[nt][0] *= a0; o[nt][1] *= a0; o[nt][2] *= a1; o[nt][3] *= a1;
        }

        #pragma unroll
        for (int kc = 0; kc < 4; kc++) {
            uint32_t pa[4];
            pa[0] = h2u(s[2 * kc    ][0], s[2 * kc    ][1]);
            pa[1] = h2u(s[2 * kc    ][2], s[2 * kc    ][3]);
            pa[2] = h2u(s[2 * kc + 1][0], s[2 * kc + 1][1]);
            pa[3] = h2u(s[2 * kc + 1][2], s[2 * kc + 1][3]);
            uint32_t kB = kc * 32;
            uint32_t b[8][2];
            #pragma unroll
            for (int ntp = 0; ntp < 4; ntp++)
                LDSM4(b[2 * ntp][0], b[2 * ntp + 1][0],
                      b[2 * ntp][1], b[2 * ntp + 1][1],
                      vfb + ntp * (16 * ATP * 4) + kB);
            #pragma unroll
            for (int nt = 0; nt < 8; nt++)
                mma16(o[nt], pa, b[nt][0], b[nt][1]);
        }

        if (j < jmaxt) {
            #pragma unroll
            for (int it = 0; it < 4; it++) {
                int d2 = d2b + it * 8;
                VBUF(nb)[(2 * d2    ) * ATP + kp] = __byte_perm(pv0[it], pv1[it], 0x5410);
                VBUF(nb)[(2 * d2 + 1) * ATP + kp] = __byte_perm(pv0[it], pv1[it], 0x7632);
            }
        }
        CPA_WAITALL();
        __syncthreads();
    }

    float inv0 = 1.f / l0, inv1 = 1.f / l1;
    uint32_t* O0 = (uint32_t*)(O + baseo + (size_t)(q0 + r    ) * EMB_);
    uint32_t* O1 = (uint32_t*)(O + baseo + (size_t)(q0 + r + 8) * EMB_);
    #pragma unroll
    for (int nt = 0; nt < 8; nt++) {
        O0[nt * 4 + t4] = h2u(o[nt][0] * inv0, o[nt][1] * inv0);
        O1[nt * 4 + t4] = h2u(o[nt][2] * inv1, o[nt][3] * inv1);
    }
}

// ---------------- launch ---------------------------------------------------
extern "C" void kernel_launch(void* const* d_in, const int* in_sizes, int n_in,
                              void* d_out, int out_size)
{
    const float* x    = (const float*)d_in[0];
    const float* ln1s = (const float*)d_in[1];
    const float* ln1b = (const float*)d_in[2];
    const float* wq   = (const float*)d_in[3];
    const float* wk   = (const float*)d_in[4];
    const float* wv   = (const float*)d_in[5];
    const float* wo   = (const float*)d_in[6];
    const float* bo   = (const float*)d_in[7];
    const float* ln2s = (const float*)d_in[8];
    const float* ln2b = (const float*)d_in[9];
    const float* w1   = (const float*)d_in[10];
    const float* b1   = (const float*)d_in[11];
    const float* w2   = (const float*)d_in[12];
    const float* b2   = (const float*)d_in[13];
    float* out = (float*)d_out;

    __half *lnh, *qkvh, *ctxh, *ffhh, *wqkvh, *woh, *w1h, *w2h;
    float *x2;
    cudaGetSymbolAddress((void**)&lnh,   g_lnh);
    cudaGetSymbolAddress((void**)&qkvh,  g_qkvh);
    cudaGetSymbolAddress((void**)&ctxh,  g_ctxh);
    cudaGetSymbolAddress((void**)&ffhh,  g_ffhh);
    cudaGetSymbolAddress((void**)&x2,    g_x2);
    cudaGetSymbolAddress((void**)&wqkvh, g_wqkvh);
    cudaGetSymbolAddress((void**)&woh,   g_woh);
    cudaGetSymbolAddress((void**)&w1h,   g_w1h);
    cudaGetSymbolAddress((void**)&w2h,   g_w2h);

    cudaFuncSetAttribute(attn_mma, cudaFuncAttributeMaxDynamicSharedMemorySize, ATTN_SMEM);
    cudaFuncSetAttribute(mmagemm<0>, cudaFuncAttributeMaxDynamicSharedMemorySize, GEMM_SMEM);
    cudaFuncSetAttribute(mmagemm<1>, cudaFuncAttributeMaxDynamicSharedMemorySize, GEMM_SMEM);
    cudaFuncSetAttribute(mmagemm<2>, cudaFuncAttributeMaxDynamicSharedMemorySize, GEMM_SMEM);

    // 0) fused weight prep
    prep_all<<<6912, dim3(32, 8)>>>(wq, wk, wv, wo, w1, w2, wqkvh, woh, w1h, w2h);
    // 1) ln1 -> half
    ln_k<<<TOK, 256>>>(x, ln1s, ln1b, lnh);
    // 2) fused QKV projection (Q pre-scaled by 0.125*log2e) -> half qkv
    mmagemm<0><<<dim3(18, 64), 256, GEMM_SMEM>>>(lnh, wqkvh, nullptr, nullptr,
                                                 qkvh, EMB_, LDQKV, 12);
    // 3) causal attention -> half ctx
    attn_mma<<<dim3(SEQ_ / 128, 4 * HEADS_), 256, ATTN_SMEM>>>(
        qkvh + 0, qkvh + 768, qkvh + 1536, ctxh);
    // 4) output projection + bias + residual -> fp32 x2
    mmagemm<1><<<dim3(6, 64), 256, GEMM_SMEM>>>(ctxh, woh, bo, x, x2,
                                                EMB_, EMB_, 12);
    // 5) ln2 -> half
    ln_k<<<TOK, 256>>>(x2, ln2s, ln2b, lnh);
    // 6) FF1 + bias + GELU -> half ffh
    mmagemm<2><<<dim3(24, 64), 256, GEMM_SMEM>>>(lnh, w1h, b1, nullptr, ffhh,
                                                 EMB_, FF_, 12);
    // 7) FF2 + bias + residual -> fp32 out
    mmagemm<1><<<dim3(6, 64), 256, GEMM_SMEM>>>(ffhh, w2h, b2, x2, out,
                                                FF_, EMB_, 48);
}

// round 12
// speedup vs baseline: 2.2081x; 1.0359x over previous
#include <cuda_runtime.h>
#include <cuda_fp16.h>
#include <cstdint>
#include <math.h>

#define TOK   8192
#define EMB_  768
#define FF_   3072
#define HEADS_ 12
#define SEQ_  2048
#define LDQKV 2304

// ---------------- scratch (device globals; no allocation allowed) ----------
__device__ __half g_lnh [TOK * EMB_];
__device__ __half g_qkvh[TOK * LDQKV];
__device__ __half g_ctxh[TOK * EMB_];
__device__ __half g_ffhh[(size_t)TOK * FF_];
__device__ float  g_x2  [TOK * EMB_];
__device__ __half g_wqkvh[LDQKV * EMB_];
__device__ __half g_woh  [EMB_ * EMB_];
__device__ __half g_w1h  [FF_ * EMB_];
__device__ __half g_w2h  [EMB_ * FF_];

// ---------------- helpers ---------------------------------------------------
__device__ __forceinline__ uint32_t s2u(const void* p) {
    uint32_t a;
    asm("{ .reg .u64 t; cvta.to.shared.u64 t, %1; cvt.u32.u64 %0, t; }" : "=r"(a) : "l"(p));
    return a;
}
__device__ __forceinline__ float gelu_f(float x) {
    const float c = 0.79788456080286535588f;
    float t = tanhf(c * (x + 0.044715f * x * x * x));
    return 0.5f * x * (1.f + t);
}
__device__ __forceinline__ uint32_t h2u(float a, float b) {
    __half2 h = __floats2half2_rn(a, b);
    return *reinterpret_cast<uint32_t*>(&h);
}
__device__ __forceinline__ void mma16(float c[4], const uint32_t a[4],
                                      uint32_t b0, uint32_t b1) {
    asm volatile("mma.sync.aligned.m16n8k16.row.col.f32.f16.f16.f32 "
        "{%0,%1,%2,%3}, {%4,%5,%6,%7}, {%8,%9}, {%0,%1,%2,%3};"
        : "+f"(c[0]), "+f"(c[1]), "+f"(c[2]), "+f"(c[3])
        : "r"(a[0]), "r"(a[1]), "r"(a[2]), "r"(a[3]), "r"(b0), "r"(b1));
}
#define LDSM4(d0, d1, d2, d3, addr) \
    asm volatile("ldmatrix.sync.aligned.m8n8.x4.shared.b16 {%0,%1,%2,%3}, [%4];" \
        : "=r"(d0), "=r"(d1), "=r"(d2), "=r"(d3) : "r"(addr))
#define LDSM4T(d0, d1, d2, d3, addr) \
    asm volatile("ldmatrix.sync.aligned.m8n8.x4.trans.shared.b16 {%0,%1,%2,%3}, [%4];" \
        : "=r"(d0), "=r"(d1), "=r"(d2), "=r"(d3) : "r"(addr))

#define CPA16(d, s) \
    asm volatile("cp.async.cg.shared.global [%0], [%1], 16;" :: "r"(d), "l"(s))
#define CPA_COMMIT()  asm volatile("cp.async.commit_group;" ::: "memory")
#define CPA_WAIT1()   asm volatile("cp.async.wait_group 1;" ::: "memory")
#define CPA_WAITALL() asm volatile("cp.async.wait_group 0;" ::: "memory")

// ---------------- fused weight prep: 6 transposes in one kernel ------------
__global__ void prep_all(const float* __restrict__ wq, const float* __restrict__ wk,
                         const float* __restrict__ wv, const float* __restrict__ wo,
                         const float* __restrict__ w1, const float* __restrict__ w2,
                         __half* __restrict__ wqkvh, __half* __restrict__ woh,
                         __half* __restrict__ w1h,  __half* __restrict__ w2h)
{
    __shared__ float t[32][33];
    int bid = blockIdx.x;
    const float* S; __half* D; int K, N, n0, k0;
    if (bid < 2304) {
        int m = bid / 576, tt = bid % 576;
        S = (m == 0) ? wq : (m == 1) ? wk : (m == 2) ? wv : wo;
        D = (m == 3) ? woh : wqkvh + (size_t)m * EMB_ * EMB_;
        K = EMB_; N = EMB_;
        n0 = (tt % 24) * 32; k0 = (tt / 24) * 32;
    } else if (bid < 4608) {
        int tt = bid - 2304;
        S = w1; D = w1h; K = EMB_; N = FF_;
        n0 = (tt % 96) * 32; k0 = (tt / 96) * 32;
    } else {
        int tt = bid - 4608;
        S = w2; D = w2h; K = FF_; N = EMB_;
        n0 = (tt % 24) * 32; k0 = (tt / 24) * 32;
    }
    int tx = threadIdx.x, ty = threadIdx.y;
    #pragma unroll
    for (int i = 0; i < 32; i += 8)
        t[ty + i][tx] = S[(size_t)(k0 + ty + i) * N + n0 + tx];
    __syncthreads();
    #pragma unroll
    for (int i = 0; i < 32; i += 8)
        D[(size_t)(n0 + ty + i) * K + k0 + tx] = __float2half_rn(t[tx][ty + i]);
}

// ---------------- layernorm: fp32 in -> half out ---------------------------
__global__ __launch_bounds__(256) void ln_k(const float* __restrict__ x,
                                            const float* __restrict__ sc,
                                            const float* __restrict__ sh,
                                            __half* __restrict__ out)
{
    int row = blockIdx.x;
    const float* xr = x + (size_t)row * EMB_;
    int t = threadIdx.x;
    float v0 = xr[t], v1 = xr[t + 256], v2 = xr[t + 512];

    __shared__ float red[8];
    float s = v0 + v1 + v2;
    #pragma unroll
    for (int o = 16; o; o >>= 1) s += __shfl_xor_sync(0xffffffffu, s, o);
    if ((t & 31) == 0) red[t >> 5] = s;
    __syncthreads();
    float mean = 0.f;
    #pragma unroll
    for (int i = 0; i < 8; i++) mean += red[i];
    mean *= (1.f / 768.f);

    float d0 = v0 - mean, d1 = v1 - mean, d2 = v2 - mean;
    float vs = d0 * d0 + d1 * d1 + d2 * d2;
    #pragma unroll
    for (int o = 16; o; o >>= 1) vs += __shfl_xor_sync(0xffffffffu, vs, o);
    __syncthreads();
    if ((t & 31) == 0) red[t >> 5] = vs;
    __syncthreads();
    float var = 0.f;
    #pragma unroll
    for (int i = 0; i < 8; i++) var += red[i];
    var *= (1.f / 768.f);
    float rstd = rsqrtf(var + 1e-5f);

    __half* orow = out + (size_t)row * EMB_;
    orow[t      ] = __float2half_rn(d0 * rstd * sc[t      ] + sh[t      ]);
    orow[t + 256] = __float2half_rn(d1 * rstd * sc[t + 256] + sh[t + 256]);
    orow[t + 512] = __float2half_rn(d2 * rstd * sc[t + 512] + sh[t + 512]);
}

// ---------------- fp16 mma.sync GEMM: C[M,N] = A[M,K] @ Bt[N,K]^T ----------
// CTA 128x128, 8 warps (2x4), warp tile 64x32. 3-stage cp.async, K=64/stage,
// ldmatrix fragment loads, ONE barrier per 64-K ktile.
#define PIT 36
#define B_OFF (128 * PIT)
#define STAGE_U32 (2 * 128 * PIT)
#define NSTG 3
#define GEMM_SMEM (NSTG * STAGE_U32 * 4)   // 110592 B

template<int EPI>   // 0: half out + Q-scale(qkv); 1: fp32 out +bias+res; 2: half out +bias+gelu
__global__ __launch_bounds__(256, 2) void mmagemm(const __half* __restrict__ A,
                                                  const __half* __restrict__ Bw,
                                                  const float* __restrict__ bias,
                                                  const float* __restrict__ res,
                                                  void* __restrict__ Cv,
                                                  int Kd, int ldc, int KT)
{
    extern __shared__ __align__(16) uint32_t smu[];
    int tid = threadIdx.x, lane = tid & 31, w = tid >> 5;
    int wm = w >> 2, wn = w & 3;
    int bm = blockIdx.y, bn = blockIdx.x;
    int gr = lane >> 2, t4 = lane & 3;
    int lrow = lane & 15;
    int lcol = (lane & 16) ? 4 : 0;

    float acc[4][4][4];
    #pragma unroll
    for (int i = 0; i < 4; i++)
        #pragma unroll
        for (int j = 0; j < 4; j++)
            #pragma unroll
            for (int e = 0; e < 4; e++) acc[i][j][e] = 0.f;

    auto issue = [&](int kt) {
        uint32_t* st = smu + (kt % NSTG) * STAGE_U32;
        int k0 = kt * 64;
        #pragma unroll
        for (int i = 0; i < 4; i++) {
            int chunk = tid + i * 256;
            int row = chunk >> 3, q = chunk & 7;
            CPA16(s2u(st + row * PIT + q * 4),
                  A + (size_t)(bm * 128 + row) * Kd + k0 + q * 8);
        }
        #pragma unroll
        for (int i = 0; i < 4; i++) {
            int chunk = tid + i * 256;
            int n = chunk >> 3, q = chunk & 7;
            CPA16(s2u(st + B_OFF + n * PIT + q * 4),
                  Bw + (size_t)(bn * 128 + n) * Kd + k0 + q * 8);
        }
    };

    issue(0); CPA_COMMIT();
    issue(1); CPA_COMMIT();

    for (int kt = 0; kt < KT; kt++) {
        CPA_WAIT1();
        __syncthreads();
        if (kt + 2 < KT) issue(kt + 2);
        CPA_COMMIT();

        const uint32_t* As = smu + (kt % NSTG) * STAGE_U32;
        uint32_t a_base = s2u(As + (wm * 64 + lrow) * PIT + lcol);
        uint32_t b_base = s2u(As + B_OFF + (wn * 32 + lrow) * PIT + lcol);

        #pragma unroll
        for (int kc = 0; kc < 4; kc++) {
            uint32_t kB = kc * 32;
            uint32_t a[4][4];
            #pragma unroll
            for (int mt = 0; mt < 4; mt++)
                LDSM4(a[mt][0], a[mt][1], a[mt][2], a[mt][3],
                      a_base + mt * (16 * PIT * 4) + kB);
            uint32_t b[4][2];
            #pragma unroll
            for (int ntp = 0; ntp < 2; ntp++)
                LDSM4(b[2 * ntp][0], b[2 * ntp + 1][0],
                      b[2 * ntp][1], b[2 * ntp + 1][1],
                      b_base + ntp * (16 * PIT * 4) + kB);
            #pragma unroll
            for (int mt = 0; mt < 4; mt++)
                #pragma unroll
                for (int nt = 0; nt < 4; nt++)
                    mma16(acc[mt][nt], a[mt], b[nt][0], b[nt][1]);
        }
    }

    // ---- epilogue ----
    float scale = 1.f;
    if (EPI == 0) scale = (bn * 128 < 768) ? 0.1803368801111204f : 1.f;  // 0.125*log2(e)
    float bv[4][2];
    if (EPI >= 1) {
        #pragma unroll
        for (int nt = 0; nt < 4; nt++) {
            int col = bn * 128 + wn * 32 + nt * 8 + t4 * 2;
            bv[nt][0] = bias[col]; bv[nt][1] = bias[col + 1];
        }
    }
    #pragma unroll
    for (int mt = 0; mt < 4; mt++) {
        #pragma unroll
        for (int rr = 0; rr < 2; rr++) {
            int row = bm * 128 + wm * 64 + mt * 16 + gr + rr * 8;
            size_t off = (size_t)row * ldc + bn * 128 + wn * 32 + t4 * 2;
            #pragma unroll
            for (int nt = 0; nt < 4; nt++) {
                float v0 = acc[mt][nt][rr * 2 + 0];
                float v1 = acc[mt][nt][rr * 2 + 1];
                if (EPI == 0) { v0 *= scale; v1 *= scale; }
                if (EPI >= 1) { v0 += bv[nt][0]; v1 += bv[nt][1]; }
                if (EPI == 2) { v0 = gelu_f(v0); v1 = gelu_f(v1); }
                if (EPI == 1) {
                    float2 r2 = *(const float2*)&res[off + nt * 8];
                    *(float2*)&((float*)Cv)[off + nt * 8] =
                        make_float2(v0 + r2.x, v1 + r2.y);
                } else {
                    *reinterpret_cast<uint32_t*>((__half*)Cv + off + nt * 8) = h2u(v0, v1);
                }
            }
        }
    }
}

// ---------------- causal flash attention, fp16 mma.sync --------------------
// BQ=128, BK=64, D=64. K and V both cp.async double-buffered, row-major
// [key][d]; V fragments via ldmatrix.trans (no manual transpose). One barrier
// per tile. LPT order. Softmax in base-2 (Q pre-scaled by 0.125*log2e).
#define ATP 36
#define KBUF(s) (smu + (s) * 2304)
#define VBUF(s) (smu + 4608 + (s) * 2304)
#define ATTN_SMEM (9216 * 4)   // 36864 B

__global__ __launch_bounds__(256, 2) void attn_mma(const __half* __restrict__ Q,
                                                   const __half* __restrict__ K,
                                                   const __half* __restrict__ V,
                                                   __half* __restrict__ O)
{
    extern __shared__ __align__(16) uint32_t smu[];

    int tid = threadIdx.x, lane = tid & 31, w = tid >> 5;
    int gr = lane >> 2, t4 = lane & 3;
    int lrow = lane & 15;
    int lcol = (lane & 16) ? 4 : 0;
    int bh = blockIdx.y, bb = bh / HEADS_, h = bh % HEADS_;
    int qb = gridDim.x - 1 - blockIdx.x;       // LPT: heavy tiles first
    int q0 = qb * 128;
    size_t baseq = (size_t)bb * SEQ_ * LDQKV + (size_t)h * 64;
    size_t baseo = (size_t)bb * SEQ_ * EMB_  + (size_t)h * 64;
    int r = w * 16 + gr;
    // ldmatrix.trans lane offset for V: tile = lane>>3 -> (key-half, d-half)
    uint32_t vt_lane = (uint32_t)(((lane & 7) + ((lane >> 3) & 1) * 8) * (ATP * 4)
                                  + (lane >> 4) * 16);

    // stage Q (pre-scaled) into smem, extract frags to regs
    for (int i = tid; i < 1024; i += 256) {
        int row = i >> 3, q = i & 7;
        CPA16(s2u(smu + row * ATP + q * 4),
              Q + baseq + (size_t)(q0 + row) * LDQKV + q * 8);
    }
    CPA_COMMIT(); CPA_WAITALL();
    __syncthreads();
    uint32_t qf[4][4];
    {
        uint32_t qbase = s2u(smu + (w * 16 + lrow) * ATP + lcol);
        #pragma unroll
        for (int kc = 0; kc < 4; kc++)
            LDSM4(qf[kc][0], qf[kc][1], qf[kc][2], qf[kc][3], qbase + kc * 32);
    }
    __syncthreads();

    auto issueKV = [&](int jj, int s) {
        for (int i = tid; i < 512; i += 256) {
            int row = i >> 3, q = i & 7;
            size_t g = baseq + (size_t)(jj * 64 + row) * LDQKV + q * 8;
            CPA16(s2u(KBUF(s) + row * ATP + q * 4), K + g);
            CPA16(s2u(VBUF(s) + row * ATP + q * 4), V + g);
        }
        CPA_COMMIT();
    };

    float m0 = -1e30f, m1 = -1e30f, l0 = 0.f, l1 = 0.f;
    float o[8][4];
    #pragma unroll
    for (int nt = 0; nt < 8; nt++)
        #pragma unroll
        for (int e = 0; e < 4; e++) o[nt][e] = 0.f;

    int jmaxt = 2 * qb + 1;
    int qlo = q0 + r;

    issueKV(0, 0);
    CPA_WAITALL();
    __syncthreads();

    for (int j = 0; j <= jmaxt; j++) {
        int buf = j & 1, nb = buf ^ 1;
        if (j < jmaxt) issueKV(j + 1, nb);

        uint32_t kfb = s2u(KBUF(buf) + lrow * ATP + lcol);
        uint32_t vfb = s2u(VBUF(buf)) + vt_lane;

        // S = Q K^T  (base-2 log units)
        float s[8][4];
        #pragma unroll
        for (int nt = 0; nt < 8; nt++)
            #pragma unroll
            for (int e = 0; e < 4; e++) s[nt][e] = 0.f;
        #pragma unroll
        for (int kc = 0; kc < 4; kc++) {
            uint32_t kB = kc * 32;
            uint32_t b[8][2];
            #pragma unroll
            for (int ntp = 0; ntp < 4; ntp++)
                LDSM4(b[2 * ntp][0], b[2 * ntp + 1][0],
                      b[2 * ntp][1], b[2 * ntp + 1][1],
                      kfb + ntp * (16 * ATP * 4) + kB);
            #pragma unroll
            for (int nt = 0; nt < 8; nt++)
                mma16(s[nt], qf[kc], b[nt][0], b[nt][1]);
        }

        // causal mask
        if (j * 64 + 63 > q0 + w * 16) {
            #pragma unroll
            for (int nt = 0; nt < 8; nt++) {
                int c0 = j * 64 + nt * 8 + 2 * t4;
                if (c0     > qlo    ) s[nt][0] = -1e30f;
                if (c0 + 1 > qlo    ) s[nt][1] = -1e30f;
                if (c0     > qlo + 8) s[nt][2] = -1e30f;
                if (c0 + 1 > qlo + 8) s[nt][3] = -1e30f;
            }
        }

        // online softmax (rows r and r+8; reduce over t4 quad)
        float mt0 = -1e30f, mt1 = -1e30f;
        #pragma unroll
        for (int nt = 0; nt < 8; nt++) {
            mt0 = fmaxf(mt0, fmaxf(s[nt][0], s[nt][1]));
            mt1 = fmaxf(mt1, fmaxf(s[nt][2], s[nt][3]));
        }
        mt0 = fmaxf(mt0, __shfl_xor_sync(0xffffffffu, mt0, 1));
        mt0 = fmaxf(mt0, __shfl_xor_sync(0xffffffffu, mt0, 2));
        mt1 = fmaxf(mt1, __shfl_xor_sync(0xffffffffu, mt1, 1));
        mt1 = fmaxf(mt1, __shfl_xor_sync(0xffffffffu, mt1, 2));
        float mn0 = fmaxf(m0, mt0), mn1 = fmaxf(m1, mt1);
        float a0 = exp2f(m0 - mn0), a1 = exp2f(m1 - mn1);
        float ps0 = 0.f, ps1 = 0.f;
        #pragma unroll
        for (int nt = 0; nt < 8; nt++) {
            s[nt][0] = exp2f(s[nt][0] - mn0); ps0 += s[nt][0];
            s[nt][1] = exp2f(s[nt][1] - mn0); ps0 += s[nt][1];
            s[nt][2] = exp2f(s[nt][2] - mn1); ps1 += s[nt][2];
            s[nt][3] = exp2f(s[nt][3] - mn1); ps1 += s[nt][3];
        }
        ps0 += __shfl_xor_sync(0xffffffffu, ps0, 1);
        ps0 += __shfl_xor_sync(0xffffffffu, ps0, 2);
        ps1 += __shfl_xor_sync(0xffffffffu, ps1, 1);
        ps1 += __shfl_xor_sync(0xffffffffu, ps1, 2);
        l0 = l0 * a0 + ps0; l1 = l1 * a1 + ps1;
        m0 = mn0; m1 = mn1;
        #pragma unroll
        for (int nt = 0; nt < 8; nt++) {
            o[nt][0] *= a0; o[nt][1] *= a0; o[nt][2] *= a1; o[nt][3] *= a1;
        }

        // O += P V  (P frags from s[] regs; V frags via ldmatrix.trans)
        #pragma unroll
        for (int kc = 0; kc < 4; kc++) {
            uint32_t pa[4];
            pa[0] = h2u(s[2 * kc    ][0], s[2 * kc    ][1]);
            pa[1] = h2u(s[2 * kc    ][2], s[2 * kc    ][3]);
            pa[2] = h2u(s[2 * kc + 1][0], s[2 * kc + 1][1]);
            pa[3] = h2u(s[2 * kc + 1][2], s[2 * kc + 1][3]);
            uint32_t kOff = (uint32_t)(kc * 16 * ATP * 4);   // key block offset
            uint32_t b[8][2];
            #pragma unroll
            for (int ntp = 0; ntp < 4; ntp++)
                LDSM4T(b[2 * ntp][0], b[2 * ntp][1],
                       b[2 * ntp + 1][0], b[2 * ntp + 1][1],
                       vfb + kOff + ntp * 32);               // d block = ntp*16 halves
            #pragma unroll
            for (int nt = 0; nt < 8; nt++)
                mma16(o[nt], pa, b[nt][0], b[nt][1]);
        }

        CPA_WAITALL();
        __syncthreads();
    }

    float inv0 = 1.f / l0, inv1 = 1.f / l1;
    uint32_t* O0 = (uint32_t*)(O + baseo + (size_t)(q0 + r    ) * EMB_);
    uint32_t* O1 = (uint32_t*)(O + baseo + (size_t)(q0 + r + 8) * EMB_);
    #pragma unroll
    for (int nt = 0; nt < 8; nt++) {
        O0[nt * 4 + t4] = h2u(o[nt][0] * inv0, o[nt][1] * inv0);
        O1[nt * 4 + t4] = h2u(o[nt][2] * inv1, o[nt][3] * inv1);
    }
}

// ---------------- launch ---------------------------------------------------
extern "C" void kernel_launch(void* const* d_in, const int* in_sizes, int n_in,
                              void* d_out, int out_size)
{
    const float* x    = (const float*)d_in[0];
    const float* ln1s = (const float*)d_in[1];
    const float* ln1b = (const float*)d_in[2];
    const float* wq   = (const float*)d_in[3];
    const float* wk   = (const float*)d_in[4];
    const float* wv   = (const float*)d_in[5];
    const float* wo   = (const float*)d_in[6];
    const float* bo   = (const float*)d_in[7];
    const float* ln2s = (const float*)d_in[8];
    const float* ln2b = (const float*)d_in[9];
    const float* w1   = (const float*)d_in[10];
    const float* b1   = (const float*)d_in[11];
    const float* w2   = (const float*)d_in[12];
    const float* b2   = (const float*)d_in[13];
    float* out = (float*)d_out;

    __half *lnh, *qkvh, *ctxh, *ffhh, *wqkvh, *woh, *w1h, *w2h;
    float *x2;
    cudaGetSymbolAddress((void**)&lnh,   g_lnh);
    cudaGetSymbolAddress((void**)&qkvh,  g_qkvh);
    cudaGetSymbolAddress((void**)&ctxh,  g_ctxh);
    cudaGetSymbolAddress((void**)&ffhh,  g_ffhh);
    cudaGetSymbolAddress((void**)&x2,    g_x2);
    cudaGetSymbolAddress((void**)&wqkvh, g_wqkvh);
    cudaGetSymbolAddress((void**)&woh,   g_woh);
    cudaGetSymbolAddress((void**)&w1h,   g_w1h);
    cudaGetSymbolAddress((void**)&w2h,   g_w2h);

    cudaFuncSetAttribute(attn_mma, cudaFuncAttributeMaxDynamicSharedMemorySize, ATTN_SMEM);
    cudaFuncSetAttribute(mmagemm<0>, cudaFuncAttributeMaxDynamicSharedMemorySize, GEMM_SMEM);
    cudaFuncSetAttribute(mmagemm<1>, cudaFuncAttributeMaxDynamicSharedMemorySize, GEMM_SMEM);
    cudaFuncSetAttribute(mmagemm<2>, cudaFuncAttributeMaxDynamicSharedMemorySize, GEMM_SMEM);

    // 0) fused weight prep
    prep_all<<<6912, dim3(32, 8)>>>(wq, wk, wv, wo, w1, w2, wqkvh, woh, w1h, w2h);
    // 1) ln1 -> half
    ln_k<<<TOK, 256>>>(x, ln1s, ln1b, lnh);
    // 2) fused QKV projection (Q pre-scaled by 0.125*log2e) -> half qkv
    mmagemm<0><<<dim3(18, 64), 256, GEMM_SMEM>>>(lnh, wqkvh, nullptr, nullptr,
                                                 qkvh, EMB_, LDQKV, 12);
    // 3) causal attention -> half ctx
    attn_mma<<<dim3(SEQ_ / 128, 4 * HEADS_), 256, ATTN_SMEM>>>(
        qkvh + 0, qkvh + 768, qkvh + 1536, ctxh);
    // 4) output projection + bias + residual -> fp32 x2
    mmagemm<1><<<dim3(6, 64), 256, GEMM_SMEM>>>(ctxh, woh, bo, x, x2,
                                                EMB_, EMB_, 12);
    // 5) ln2 -> half
    ln_k<<<TOK, 256>>>(x2, ln2s, ln2b, lnh);
    // 6) FF1 + bias + GELU -> half ffh
    mmagemm<2><<<dim3(24, 64), 256, GEMM_SMEM>>>(lnh, w1h, b1, nullptr, ffhh,
                                                 EMB_, FF_, 12);
    // 7) FF2 + bias + residual -> fp32 out
    mmagemm<1><<<dim3(6, 64), 256, GEMM_SMEM>>>(ffhh, w2h, b2, x2, out,
                                                FF_, EMB_, 48);
}